// round 4
// baseline (speedup 1.0000x reference)
#include <cuda_runtime.h>
#include <math.h>

#define NN  4096
#define EMB 256
#define NH  4
#define HC  64
#define TI  128
#define TJ  64
#define CSTR (2*TI + 4)   // c_dup row stride in floats (260) — 16B aligned

typedef unsigned long long ull;

// ---- device scratch (no allocations allowed) ----
__device__ float    g_h[NN*EMB];            // h = x @ W_lin
__device__ float    g_att[NN*EMB];          // attention output (+bias_att)
__device__ float    g_y[NN*EMB];            // pre-LN linear output
__device__ float    g_r[NH*NN];             // e^{0.8 s_i}
__device__ float    g_a[NH*NN];             // e^{t_j}
__device__ float    g_b[NH*NN];             // e^{0.2 t_j}
__device__ unsigned g_adjbits[NN*(NN/32)];  // adjacency bitmask, diag forced 1

__device__ __forceinline__ void fma2(ull& d, ull a, ull b) {
    asm("fma.rn.f32x2 %0, %1, %2, %0;" : "+l"(d) : "l"(a), "l"(b));
}
__device__ __forceinline__ ull dup2(float x) {
    ull r; asm("mov.b64 %0, {%1, %1};" : "=l"(r) : "f"(x)); return r;
}

// ---------------------------------------------------------------------------
// fp32 GEMM (f32x2 inner): Co[M,Nc] = A[M,K] @ B[K,Nc] (+ bias). 64x64 tile.
// ---------------------------------------------------------------------------
__global__ __launch_bounds__(256) void gemm_bias_kernel(
    const float* __restrict__ A, const float* __restrict__ B,
    const float* __restrict__ bias, float* __restrict__ Co,
    int M, int Nc, int K)
{
    __shared__ float as[16][68];   // [k][m] transposed
    __shared__ float bs[16][68];   // [k][n]
    const int m0 = blockIdx.y * 64, n0 = blockIdx.x * 64;
    const int tid = threadIdx.x;
    const int ty = tid >> 4, tx = tid & 15;

    ull acc[4][2];
#pragma unroll
    for (int i = 0; i < 4; i++) { acc[i][0] = 0ull; acc[i][1] = 0ull; }

    for (int k0 = 0; k0 < K; k0 += 16) {
        {
            int r = tid >> 2, c4 = tid & 3;
            float4 v = *(const float4*)&A[(m0 + r) * K + k0 + c4 * 4];
            as[c4*4+0][r] = v.x; as[c4*4+1][r] = v.y;
            as[c4*4+2][r] = v.z; as[c4*4+3][r] = v.w;
        }
        {
            int r = tid >> 4, c4 = tid & 15;
            *(float4*)&bs[r][c4*4] = *(const float4*)&B[(k0 + r) * Nc + n0 + c4 * 4];
        }
        __syncthreads();
#pragma unroll
        for (int k = 0; k < 16; k++) {
            float4 av = *(const float4*)&as[k][ty * 4];
            ulonglong2 bv = *(const ulonglong2*)&bs[k][tx * 4];
            ull ad[4] = { dup2(av.x), dup2(av.y), dup2(av.z), dup2(av.w) };
#pragma unroll
            for (int i = 0; i < 4; i++) {
                fma2(acc[i][0], ad[i], bv.x);
                fma2(acc[i][1], ad[i], bv.y);
            }
        }
        __syncthreads();
    }
#pragma unroll
    for (int i = 0; i < 4; i++) {
        int row = m0 + ty * 4 + i;
#pragma unroll
        for (int p = 0; p < 2; p++) {
            ull v = acc[i][p];
            float lo = __uint_as_float((unsigned)(v & 0xffffffffull));
            float hi = __uint_as_float((unsigned)(v >> 32));
            int col = n0 + tx * 4 + p * 2;
            float b0 = bias ? bias[col]     : 0.f;
            float b1 = bias ? bias[col + 1] : 0.f;
            Co[row * Nc + col]     = lo + b0;
            Co[row * Nc + col + 1] = hi + b1;
        }
    }
}

// ---------------------------------------------------------------------------
// adj -> bitmask (with forced self-loop on the diagonal)
// ---------------------------------------------------------------------------
__global__ __launch_bounds__(256) void adjbits_kernel(const int* __restrict__ adj)
{
    int row  = blockIdx.x;
    int lane = threadIdx.x & 31;
    int w    = threadIdx.x >> 5;
#pragma unroll
    for (int wd = w; wd < NN/32; wd += 8) {
        int v = adj[(long)row * NN + wd * 32 + lane];
        unsigned bits = __ballot_sync(0xffffffffu, v != 0);
        if ((row >> 5) == wd) bits |= 1u << (row & 31);   // self loop
        if (lane == 0) g_adjbits[row * (NN/32) + wd] = bits;
    }
}

// ---------------------------------------------------------------------------
// Prep: per (head,node): s = h.att_dst, t = h.att_src -> r=e^{0.8s}, a=e^t, b=e^{0.2t}
// ---------------------------------------------------------------------------
__global__ __launch_bounds__(256) void prep_kernel(
    const float* __restrict__ att_src, const float* __restrict__ att_dst)
{
    int wid  = blockIdx.x * 8 + (threadIdx.x >> 5);
    int lane = threadIdx.x & 31;
    int hd = wid >> 12;
    int n  = wid & (NN - 1);
    const float* hp = g_h + n * EMB + hd * HC;
    float h0 = hp[lane], h1 = hp[lane + 32];
    float s = h0 * att_dst[hd*HC + lane] + h1 * att_dst[hd*HC + lane + 32];
    float t = h0 * att_src[hd*HC + lane] + h1 * att_src[hd*HC + lane + 32];
#pragma unroll
    for (int o = 16; o; o >>= 1) {
        s += __shfl_xor_sync(0xffffffffu, s, o);
        t += __shfl_xor_sync(0xffffffffu, t, o);
    }
    if (lane == 0) {
        g_r[wid] = expf(0.8f * s);
        g_a[wid] = expf(t);
        g_b[wid] = expf(0.2f * t);
    }
}

// ---------------------------------------------------------------------------
// Fused GAT aggregation: 512 threads = 2 groups x 256. Group g handles j-tiles
// (2t+g)*64. Phase C writes DUPLICATED (c,c) pairs into c_dup so the GEMM
// loads packed operands directly (no per-thread dup movs). Per-thread GEMM
// tile 4i x 8c in f32x2. Merge + normalize + bias at the end.
// ---------------------------------------------------------------------------
__global__ __launch_bounds__(512) void gat_kernel(const float* __restrict__ bias_att)
{
    extern __shared__ float sm[];
    float* ab    = sm;                        // [NN] float2 pairs -> 2*NN floats
    float* base0 = sm + 2 * NN;
    const int GSZ = TJ * CSTR + TJ * HC;      // 20736 floats per group

    const int hd = blockIdx.y;
    const int i0 = blockIdx.x * TI;
    const int tid = threadIdx.x;
    const int g   = tid >> 8;                 // group 0/1
    const int gt  = tid & 255;                // thread-in-group
    float* c_dup = base0 + g * GSZ;
    float* h_sm  = c_dup + TJ * CSTR;

    const float* ga = g_a + hd * NN;
    const float* gb = g_b + hd * NN;

    // preload a/b for the whole head (shared by both groups)
    for (int k = tid; k < NN; k += 512)
        ((float2*)ab)[k] = make_float2(ga[k], gb[k]);

    // phase-C mapping: 2 threads per dest row, 32 source cols each
    const int row = gt & 127;
    const int jh  = gt >> 7;                  // 0/1: which 32-wide half
    const float ri = g_r[hd * NN + i0 + row];
    const unsigned* abits = g_adjbits + (long)(i0 + row) * (NN/32);

    // GEMM mapping: 4 rows x 8 cols per thread
    const int ty = gt >> 3;                   // 0..31 -> i base ty*4
    const int tx = gt & 7;                    // 0..7  -> c base tx*8
    ull acc[4][4];
#pragma unroll
    for (int i = 0; i < 4; i++)
#pragma unroll
        for (int j = 0; j < 4; j++) acc[i][j] = 0ull;
    float dreg = 0.f;

    __syncthreads();   // ab ready

    for (int t = 0; t < 32; t++) {
        const int j0 = (2 * t + g) * TJ;

        asm volatile("bar.sync %0, 256;" :: "r"(g + 1) : "memory");  // bufs free

        // load h tile: 64 rows x 64 floats = 1024 float4 slots, 256 threads
#pragma unroll
        for (int rr = 0; rr < 4; rr++) {
            int e = rr * 256 + gt;            // 0..1023
            int j = e >> 4, c4 = e & 15;
            *(float4*)&h_sm[j * HC + c4 * 4] =
                *(const float4*)&g_h[(j0 + j) * EMB + hd * HC + c4 * 4];
        }

        // phase C: row `row`, cols [j0 + jh*32, +32), duplicated store
        {
            unsigned wbits = abits[(j0 >> 5) + jh];
            const float2* abj = (const float2*)ab + j0 + jh * 32;
            float* cbase = c_dup + jh * 32 * CSTR + 2 * row;
#pragma unroll
            for (int jj = 0; jj < 32; jj++) {
                float2 p = abj[jj];
                float v = fmaxf(ri * p.x, p.y);
                float cv = ((wbits >> jj) & 1u) ? v : 0.f;
                *(ull*)(cbase + jj * CSTR) = dup2(cv);
                dreg += cv;
            }
        }

        asm volatile("bar.sync %0, 256;" :: "r"(g + 1) : "memory");  // bufs ready

        // GEMM: acc[ii][cc] += c[j][ty*4+ii] * h[j][tx*8+2cc..]
        const float* cb = c_dup + 8 * ty;     // 2*(ty*4)
        const float* hb = h_sm + 8 * tx;
#pragma unroll 4
        for (int j = 0; j < TJ; j++) {
            ulonglong2 cA = *(const ulonglong2*)(cb + j * CSTR);      // (c0,c0),(c1,c1)
            ulonglong2 cB = *(const ulonglong2*)(cb + j * CSTR + 4);  // (c2,c2),(c3,c3)
            ulonglong2 hA = *(const ulonglong2*)(hb + j * HC);
            ulonglong2 hB = *(const ulonglong2*)(hb + j * HC + 4);
            ull cd[4] = { cA.x, cA.y, cB.x, cB.y };
#pragma unroll
            for (int ii = 0; ii < 4; ii++) {
                fma2(acc[ii][0], cd[ii], hA.x);
                fma2(acc[ii][1], cd[ii], hA.y);
                fma2(acc[ii][2], cd[ii], hB.x);
                fma2(acc[ii][3], cd[ii], hB.y);
            }
        }
    }

    __syncthreads();   // all tiles done

    // merge region reuses group1's c_dup space
    const int MS = 66;                        // merge row stride (floats)
    float* mrg  = base0 + GSZ;                // 128*66 = 8448 floats
    float* d_sm = mrg + TI * MS;              // 4*128 floats

    d_sm[(g * 2 + jh) * TI + row] = dreg;
    if (g == 1) {
#pragma unroll
        for (int ii = 0; ii < 4; ii++) {
            int i = ty * 4 + ii;
#pragma unroll
            for (int cc = 0; cc < 4; cc++)
                *(ull*)&mrg[i * MS + tx * 8 + cc * 2] = acc[ii][cc];
        }
    }
    __syncthreads();

    if (g == 0) {
#pragma unroll
        for (int ii = 0; ii < 4; ii++) {
            int i = ty * 4 + ii;
            float inv = 1.0f / (d_sm[i] + d_sm[TI + i] + d_sm[2*TI + i] + d_sm[3*TI + i]);
            int grow = i0 + i;
            float o[8];
#pragma unroll
            for (int cc = 0; cc < 4; cc++) {
                ull v = acc[ii][cc];
                ull m = *(const ull*)&mrg[i * MS + tx * 8 + cc * 2];
                float lo = __uint_as_float((unsigned)(v & 0xffffffffull))
                         + __uint_as_float((unsigned)(m & 0xffffffffull));
                float hi = __uint_as_float((unsigned)(v >> 32))
                         + __uint_as_float((unsigned)(m >> 32));
                int col = hd * HC + tx * 8 + cc * 2;
                o[cc*2]   = lo * inv + __ldg(bias_att + col);
                o[cc*2+1] = hi * inv + __ldg(bias_att + col + 1);
            }
            float* dst = g_att + (long)grow * EMB + hd * HC + tx * 8;
            *(float4*)dst       = make_float4(o[0], o[1], o[2], o[3]);
            *(float4*)(dst + 4) = make_float4(o[4], o[5], o[6], o[7]);
        }
    }
}

// ---------------------------------------------------------------------------
// LayerNorm over last dim (256), one block per row.
// ---------------------------------------------------------------------------
__global__ __launch_bounds__(256) void ln_kernel(
    const float* __restrict__ gamma, const float* __restrict__ beta,
    float* __restrict__ out)
{
    __shared__ float red1[8], red2[8];
    int row = blockIdx.x;
    int tid = threadIdx.x;
    float v = g_y[row * EMB + tid];

    float s = v;
#pragma unroll
    for (int o = 16; o; o >>= 1) s += __shfl_xor_sync(0xffffffffu, s, o);
    if ((tid & 31) == 0) red1[tid >> 5] = s;
    __syncthreads();
    float mu = 0.f;
#pragma unroll
    for (int k = 0; k < 8; k++) mu += red1[k];
    mu *= (1.0f / EMB);

    float d = v - mu;
    float q = d * d;
#pragma unroll
    for (int o = 16; o; o >>= 1) q += __shfl_xor_sync(0xffffffffu, q, o);
    if ((tid & 31) == 0) red2[tid >> 5] = q;
    __syncthreads();
    float var = 0.f;
#pragma unroll
    for (int k = 0; k < 8; k++) var += red2[k];
    var *= (1.0f / EMB);

    out[row * EMB + tid] = d * rsqrtf(var + 1e-5f) * gamma[tid] + beta[tid];
}

// ---------------------------------------------------------------------------
extern "C" void kernel_launch(void* const* d_in, const int* in_sizes, int n_in,
                              void* d_out, int out_size)
{
    const float* x        = (const float*)d_in[0];
    const int*   adj      = (const int*)  d_in[1];
    const float* W_lin    = (const float*)d_in[2];
    const float* att_src  = (const float*)d_in[3];
    const float* att_dst  = (const float*)d_in[4];
    const float* bias_att = (const float*)d_in[5];
    const float* W_out    = (const float*)d_in[6];
    const float* b_out    = (const float*)d_in[7];
    const float* gamma    = (const float*)d_in[8];
    const float* beta     = (const float*)d_in[9];
    float* out = (float*)d_out;

    float *p_h, *p_att, *p_y;
    cudaGetSymbolAddress((void**)&p_h,   g_h);
    cudaGetSymbolAddress((void**)&p_att, g_att);
    cudaGetSymbolAddress((void**)&p_y,   g_y);

    const int GSZ = TJ * CSTR + TJ * HC;
    const int gat_smem = (2*NN + 2*GSZ) * (int)sizeof(float);   // 198656 B
    cudaFuncSetAttribute(gat_kernel, cudaFuncAttributeMaxDynamicSharedMemorySize, gat_smem);

    dim3 gemm_grid(EMB / 64, NN / 64);  // (4, 64)

    // 1) h = x @ W_lin
    gemm_bias_kernel<<<gemm_grid, 256>>>(x, W_lin, nullptr, p_h, NN, EMB, EMB);
    adjbits_kernel<<<NN, 256>>>(adj);
    prep_kernel<<<(NH * NN) / 8, 256>>>(att_src, att_dst);
    // 2) fused masked-softmax aggregation (+bias_att)
    dim3 gat_grid(NN / TI, NH);
    gat_kernel<<<gat_grid, 512, gat_smem>>>(bias_att);
    // 3) y = att @ W_out + b_out
    gemm_bias_kernel<<<gemm_grid, 256>>>(p_att, W_out, b_out, p_y, NN, EMB, EMB);
    // 4) LayerNorm -> out
    ln_kernel<<<NN, 256>>>(gamma, beta, out);
}

// round 6
// speedup vs baseline: 2.1618x; 2.1618x over previous
#include <cuda_runtime.h>
#include <cuda_bf16.h>
#include <math.h>

#define NN  4096
#define EMB 256
#define NH  4
#define HC  64

typedef unsigned long long ull;

// ---- device scratch (no allocations allowed) ----
__device__ float    g_h[NN*EMB];
__device__ float    g_att[NN*EMB];
__device__ float    g_y[NN*EMB];
__device__ float    g_r[NH*NN];                 // e^{0.8 s_i}
__device__ float    g_ab[NH*NN*2];              // interleaved (e^{t_j}, e^{0.2 t_j})
__device__ unsigned g_adjbits[NN*(NN/32)];      // adjacency bitmask, diag=1
__device__ __nv_bfloat16 g_hThi[(size_t)NH*HC*NN];   // h transposed, bf16 hi (trunc)
__device__ __nv_bfloat16 g_hTlo[(size_t)NH*HC*NN];   // h transposed, bf16 lo (residual)

__device__ __forceinline__ unsigned swz(unsigned o) { return o ^ ((o >> 3) & 0x70); }

__device__ __forceinline__ void ldsm4(unsigned& r0, unsigned& r1, unsigned& r2, unsigned& r3,
                                      unsigned a) {
    asm volatile("ldmatrix.sync.aligned.m8n8.x4.shared.b16 {%0,%1,%2,%3}, [%4];"
        : "=r"(r0), "=r"(r1), "=r"(r2), "=r"(r3) : "r"(a));
}
__device__ __forceinline__ void mma16816(float* d, unsigned a0, unsigned a1, unsigned a2,
                                         unsigned a3, unsigned b0, unsigned b1) {
    asm volatile("mma.sync.aligned.m16n8k16.row.col.f32.bf16.bf16.f32 "
        "{%0,%1,%2,%3}, {%4,%5,%6,%7}, {%8,%9}, {%0,%1,%2,%3};"
        : "+f"(d[0]), "+f"(d[1]), "+f"(d[2]), "+f"(d[3])
        : "r"(a0), "r"(a1), "r"(a2), "r"(a3), "r"(b0), "r"(b1));
}

// ---------------------------------------------------------------------------
// fp32 GEMM: Co[M,Nc] = A[M,K] @ B[K,Nc] (+ bias). 64x64 tile, 256 thr.
// ---------------------------------------------------------------------------
__global__ __launch_bounds__(256) void gemm_bias_kernel(
    const float* __restrict__ A, const float* __restrict__ B,
    const float* __restrict__ bias, float* __restrict__ Co,
    int M, int Nc, int K)
{
    __shared__ float as[16][68];
    __shared__ float bs[16][68];
    const int m0 = blockIdx.y * 64, n0 = blockIdx.x * 64;
    const int tid = threadIdx.x;
    const int ty = tid >> 4, tx = tid & 15;

    float acc[4][4];
#pragma unroll
    for (int i = 0; i < 4; i++)
#pragma unroll
        for (int j = 0; j < 4; j++) acc[i][j] = 0.f;

    for (int k0 = 0; k0 < K; k0 += 16) {
        {
            int r = tid >> 2, c4 = tid & 3;
            float4 v = *(const float4*)&A[(m0 + r) * K + k0 + c4 * 4];
            as[c4*4+0][r] = v.x; as[c4*4+1][r] = v.y;
            as[c4*4+2][r] = v.z; as[c4*4+3][r] = v.w;
        }
        {
            int r = tid >> 4, c4 = tid & 15;
            *(float4*)&bs[r][c4*4] = *(const float4*)&B[(k0 + r) * Nc + n0 + c4 * 4];
        }
        __syncthreads();
#pragma unroll
        for (int k = 0; k < 16; k++) {
            float4 av = *(const float4*)&as[k][ty * 4];
            float4 bv = *(const float4*)&bs[k][tx * 4];
            float a4[4] = {av.x, av.y, av.z, av.w};
            float b4[4] = {bv.x, bv.y, bv.z, bv.w};
#pragma unroll
            for (int i = 0; i < 4; i++)
#pragma unroll
                for (int j = 0; j < 4; j++) acc[i][j] += a4[i] * b4[j];
        }
        __syncthreads();
    }
#pragma unroll
    for (int i = 0; i < 4; i++) {
        int row = m0 + ty * 4 + i;
#pragma unroll
        for (int j = 0; j < 4; j++) {
            int col = n0 + tx * 4 + j;
            float v = acc[i][j];
            if (bias) v += bias[col];
            Co[row * Nc + col] = v;
        }
    }
}

// ---------------------------------------------------------------------------
// adj -> bitmask (forced self-loop)
// ---------------------------------------------------------------------------
__global__ __launch_bounds__(256) void adjbits_kernel(const int* __restrict__ adj)
{
    int row  = blockIdx.x;
    int lane = threadIdx.x & 31;
    int w    = threadIdx.x >> 5;
#pragma unroll
    for (int wd = w; wd < NN/32; wd += 8) {
        int v = adj[(long)row * NN + wd * 32 + lane];
        unsigned bits = __ballot_sync(0xffffffffu, v != 0);
        if ((row >> 5) == wd) bits |= 1u << (row & 31);
        if (lane == 0) g_adjbits[row * (NN/32) + wd] = bits;
    }
}

// ---------------------------------------------------------------------------
// Prep: per (head,node) r = e^{0.8s}, ab = (e^t, e^{0.2t})
// ---------------------------------------------------------------------------
__global__ __launch_bounds__(256) void prep_kernel(
    const float* __restrict__ att_src, const float* __restrict__ att_dst)
{
    int wid  = blockIdx.x * 8 + (threadIdx.x >> 5);
    int lane = threadIdx.x & 31;
    int hd = wid >> 12;
    int n  = wid & (NN - 1);
    const float* hp = g_h + n * EMB + hd * HC;
    float h0 = hp[lane], h1 = hp[lane + 32];
    float s = h0 * att_dst[hd*HC + lane] + h1 * att_dst[hd*HC + lane + 32];
    float t = h0 * att_src[hd*HC + lane] + h1 * att_src[hd*HC + lane + 32];
#pragma unroll
    for (int o = 16; o; o >>= 1) {
        s += __shfl_xor_sync(0xffffffffu, s, o);
        t += __shfl_xor_sync(0xffffffffu, t, o);
    }
    if (lane == 0) {
        g_r[wid] = expf(0.8f * s);
        g_ab[2*wid]   = expf(t);
        g_ab[2*wid+1] = expf(0.2f * t);
    }
}

// ---------------------------------------------------------------------------
// h -> transposed split-bf16: g_hThi/lo[hd][c][j]. Block: one head x 64 j.
// ---------------------------------------------------------------------------
__global__ __launch_bounds__(256) void ht_kernel()
{
    __shared__ float s[64][65];
    const int hd = blockIdx.y, jt = blockIdx.x * 64;
    const int t = threadIdx.x;
    {
        int r = t >> 2, cq = t & 3;
        const float4* src = (const float4*)(g_h + (size_t)(jt + r) * EMB + hd * HC + cq * 16);
#pragma unroll
        for (int u = 0; u < 4; u++) {
            float4 v = src[u];
            int cb = cq * 16 + u * 4;
            s[r][cb] = v.x; s[r][cb+1] = v.y; s[r][cb+2] = v.z; s[r][cb+3] = v.w;
        }
    }
    __syncthreads();
    int c = t >> 2, jq = t & 3;
    unsigned hi[8], lo[8];
#pragma unroll
    for (int e = 0; e < 8; e++) {
        float f0 = s[jq*16 + 2*e][c];
        float f1 = s[jq*16 + 2*e + 1][c];
        unsigned u0 = __float_as_uint(f0), u1 = __float_as_uint(f1);
        hi[e] = __byte_perm(u0, u1, 0x7632);
        float r0 = f0 - __uint_as_float(u0 & 0xffff0000u);
        float r1 = f1 - __uint_as_float(u1 & 0xffff0000u);
        asm("cvt.rn.bf16x2.f32 %0, %1, %2;" : "=r"(lo[e]) : "f"(r1), "f"(r0));
    }
    size_t o = (size_t)(hd * HC + c) * NN + jt + jq * 16;
    *(uint4*)(g_hThi + o)       = make_uint4(hi[0], hi[1], hi[2], hi[3]);
    *((uint4*)(g_hThi + o) + 1) = make_uint4(hi[4], hi[5], hi[6], hi[7]);
    *(uint4*)(g_hTlo + o)       = make_uint4(lo[0], lo[1], lo[2], lo[3]);
    *((uint4*)(g_hTlo + o) + 1) = make_uint4(lo[4], lo[5], lo[6], lo[7]);
}

// ---------------------------------------------------------------------------
// GAT aggregation via mma.sync bf16 (split hi/lo, 3 products).
// Block = 128 rows x 1 head, 256 threads (8 warps x 16 rows).
// ---------------------------------------------------------------------------
#define SM_AB   0        // 32768 B: (a,b) pairs for whole head
#define SM_AHI  32768    // 16384 B: c tile [128][64] bf16 hi, SW128
#define SM_ALO  49152    // 16384 B
#define SM_BHI  65536    //  8192 B: hT tile [64 n][64 k] bf16 hi, SW128
#define SM_BLO  73728    //  8192 B
#define SM_D    81920    //  1024 B: per-(row,half) denominators
#define SM_TOT  82944

__global__ __launch_bounds__(256) void gat_mma_kernel(const float* __restrict__ bias_att)
{
    extern __shared__ char smc[];
    const unsigned sb = (unsigned)__cvta_generic_to_shared(smc);
    const int tid  = threadIdx.x;
    const int hd   = blockIdx.y;
    const int i0   = blockIdx.x * 128;
    const int lane = tid & 31;
    const int warp = tid >> 5;
    const int m0   = warp * 16;

    // preload (a,b) pairs for this head into smem
    {
        const float4* src = (const float4*)(g_ab + (size_t)hd * NN * 2);
        float4* dst = (float4*)(smc + SM_AB);
        for (int k = tid; k < NN / 2; k += 256) dst[k] = src[k];
    }

    // phase-C mapping: 2 threads per dest row, 32 j each
    const int row  = tid >> 1;
    const int half = tid & 1;
    const float ri = g_r[hd * NN + i0 + row];
    const unsigned* abw = g_adjbits + (size_t)(i0 + row) * (NN / 32);
    const float4* abt4  = (const float4*)(smc + SM_AB);
    float dreg = 0.f;

    // mma fragment addressing constants
    const int grp = lane >> 3, lr = lane & 7;
    const unsigned arow = (unsigned)(m0 + lr + ((grp & 1) << 3));
    const unsigned khalf = (unsigned)((grp >> 1) << 4);

    const __nv_bfloat16* bhsrc0 = g_hThi + (size_t)hd * HC * NN;
    const __nv_bfloat16* blsrc0 = g_hTlo + (size_t)hd * HC * NN;

    float acc[8][4];
#pragma unroll
    for (int n = 0; n < 8; n++)
#pragma unroll
        for (int e = 0; e < 4; e++) acc[n][e] = 0.f;

    __syncthreads();   // ab ready

    for (int t = 0; t < 64; t++) {
        const int j0 = t * 64;
        __syncthreads();   // smem tiles free (prev mma reads done)

        // B tiles: hT [64 c][64 j] bf16 hi/lo, 128B rows, SW128
#pragma unroll
        for (int r = 0; r < 2; r++) {
            int ch = tid + r * 256;
            int c = ch >> 3, q = ch & 7;
            unsigned so = swz((unsigned)(c * 128 + q * 16));
            *(uint4*)(smc + SM_BHI + so) = __ldg((const uint4*)(bhsrc0 + (size_t)c * NN + j0 + q * 8));
            *(uint4*)(smc + SM_BLO + so) = __ldg((const uint4*)(blsrc0 + (size_t)c * NN + j0 + q * 8));
        }

        // A tile: c[row][j] masked weights, split bf16, 32 j per thread
        {
            unsigned wb = abw[(j0 >> 5) + half];
            const float4* abt = abt4 + (j0 >> 1) + half * 16;
#pragma unroll
            for (int q = 0; q < 4; q++) {
                unsigned hi4[4], lo4[4];
#pragma unroll
                for (int p = 0; p < 4; p++) {
                    float4 v = abt[q * 4 + p];
                    int sh = q * 8 + p * 2;
                    float c0 = ((wb >> sh) & 1u)       ? fmaxf(ri * v.x, v.y) : 0.f;
                    float c1 = ((wb >> (sh + 1)) & 1u) ? fmaxf(ri * v.z, v.w) : 0.f;
                    dreg += c0 + c1;
                    unsigned u0 = __float_as_uint(c0), u1 = __float_as_uint(c1);
                    hi4[p] = __byte_perm(u0, u1, 0x7632);
                    float r0 = c0 - __uint_as_float(u0 & 0xffff0000u);
                    float r1 = c1 - __uint_as_float(u1 & 0xffff0000u);
                    asm("cvt.rn.bf16x2.f32 %0, %1, %2;" : "=r"(lo4[p]) : "f"(r1), "f"(r0));
                }
                unsigned so = swz((unsigned)(row * 128 + half * 64 + q * 16));
                *(uint4*)(smc + SM_AHI + so) = make_uint4(hi4[0], hi4[1], hi4[2], hi4[3]);
                *(uint4*)(smc + SM_ALO + so) = make_uint4(lo4[0], lo4[1], lo4[2], lo4[3]);
            }
        }
        __syncthreads();   // tiles ready

        // mma phase: warp owns rows [m0, m0+16)
#pragma unroll
        for (int kk = 0; kk < 4; kk++) {
            unsigned aoff = swz(arow * 128 + (unsigned)(kk * 32) + khalf);
            unsigned ah0, ah1, ah2, ah3, al0, al1, al2, al3;
            ldsm4(ah0, ah1, ah2, ah3, sb + SM_AHI + aoff);
            ldsm4(al0, al1, al2, al3, sb + SM_ALO + aoff);
#pragma unroll
            for (int np = 0; np < 4; np++) {
                unsigned nrow = (unsigned)(np * 16 + lr + ((grp & 1) << 3));
                unsigned boff = swz(nrow * 128 + (unsigned)(kk * 32) + khalf);
                unsigned bh0, bh1, bh2, bh3, bl0, bl1, bl2, bl3;
                ldsm4(bh0, bh1, bh2, bh3, sb + SM_BHI + boff);
                ldsm4(bl0, bl1, bl2, bl3, sb + SM_BLO + boff);
                mma16816(acc[2*np],   ah0, ah1, ah2, ah3, bh0, bh2);
                mma16816(acc[2*np],   ah0, ah1, ah2, ah3, bl0, bl2);
                mma16816(acc[2*np],   al0, al1, al2, al3, bh0, bh2);
                mma16816(acc[2*np+1], ah0, ah1, ah2, ah3, bh1, bh3);
                mma16816(acc[2*np+1], ah0, ah1, ah2, ah3, bl1, bl3);
                mma16816(acc[2*np+1], al0, al1, al2, al3, bh1, bh3);
            }
        }
    }

    // denominators
    ((float*)(smc + SM_D))[tid] = dreg;
    __syncthreads();

    // epilogue: D thread layout: rows m0 + lane/4 and +8; cols n*8 + (lane%4)*2
    {
        const float* dsm = (const float*)(smc + SM_D);
        int r0 = m0 + (lane >> 2);
        int r1 = r0 + 8;
        float inv0 = 1.0f / (dsm[2*r0] + dsm[2*r0 + 1]);
        float inv1 = 1.0f / (dsm[2*r1] + dsm[2*r1 + 1]);
        float* d0 = g_att + (size_t)(i0 + r0) * EMB + hd * HC;
        float* d1 = g_att + (size_t)(i0 + r1) * EMB + hd * HC;
        int cbase = (lane & 3) * 2;
#pragma unroll
        for (int nn = 0; nn < 8; nn++) {
            int col = nn * 8 + cbase;
            float b0 = __ldg(bias_att + hd * HC + col);
            float b1 = __ldg(bias_att + hd * HC + col + 1);
            *(float2*)(d0 + col) = make_float2(acc[nn][0] * inv0 + b0,
                                               acc[nn][1] * inv0 + b1);
            *(float2*)(d1 + col) = make_float2(acc[nn][2] * inv1 + b0,
                                               acc[nn][3] * inv1 + b1);
        }
    }
}

// ---------------------------------------------------------------------------
// LayerNorm over last dim (256), one block per row.
// ---------------------------------------------------------------------------
__global__ __launch_bounds__(256) void ln_kernel(
    const float* __restrict__ gamma, const float* __restrict__ beta,
    float* __restrict__ out)
{
    __shared__ float red1[8], red2[8];
    int row = blockIdx.x;
    int tid = threadIdx.x;
    float v = g_y[row * EMB + tid];

    float s = v;
#pragma unroll
    for (int o = 16; o; o >>= 1) s += __shfl_xor_sync(0xffffffffu, s, o);
    if ((tid & 31) == 0) red1[tid >> 5] = s;
    __syncthreads();
    float mu = 0.f;
#pragma unroll
    for (int k = 0; k < 8; k++) mu += red1[k];
    mu *= (1.0f / EMB);

    float d = v - mu;
    float q = d * d;
#pragma unroll
    for (int o = 16; o; o >>= 1) q += __shfl_xor_sync(0xffffffffu, q, o);
    if ((tid & 31) == 0) red2[tid >> 5] = q;
    __syncthreads();
    float var = 0.f;
#pragma unroll
    for (int k = 0; k < 8; k++) var += red2[k];
    var *= (1.0f / EMB);

    out[row * EMB + tid] = d * rsqrtf(var + 1e-5f) * gamma[tid] + beta[tid];
}

// ---------------------------------------------------------------------------
extern "C" void kernel_launch(void* const* d_in, const int* in_sizes, int n_in,
                              void* d_out, int out_size)
{
    const float* x        = (const float*)d_in[0];
    const int*   adj      = (const int*)  d_in[1];
    const float* W_lin    = (const float*)d_in[2];
    const float* att_src  = (const float*)d_in[3];
    const float* att_dst  = (const float*)d_in[4];
    const float* bias_att = (const float*)d_in[5];
    const float* W_out    = (const float*)d_in[6];
    const float* b_out    = (const float*)d_in[7];
    const float* gamma    = (const float*)d_in[8];
    const float* beta     = (const float*)d_in[9];
    float* out = (float*)d_out;

    float *p_h, *p_att, *p_y;
    cudaGetSymbolAddress((void**)&p_h,   g_h);
    cudaGetSymbolAddress((void**)&p_att, g_att);
    cudaGetSymbolAddress((void**)&p_y,   g_y);

    cudaFuncSetAttribute(gat_mma_kernel, cudaFuncAttributeMaxDynamicSharedMemorySize, SM_TOT);

    dim3 gemm_grid(EMB / 64, NN / 64);  // (4, 64)

    // 1) h = x @ W_lin
    gemm_bias_kernel<<<gemm_grid, 256>>>(x, W_lin, nullptr, p_h, NN, EMB, EMB);
    adjbits_kernel<<<NN, 256>>>(adj);
    prep_kernel<<<(NH * NN) / 8, 256>>>(att_src, att_dst);
    ht_kernel<<<dim3(NN / 64, NH), 256>>>();
    // 2) HMMA masked-softmax aggregation (+bias_att)
    gat_mma_kernel<<<dim3(NN / 128, NH), 256, SM_TOT>>>(bias_att);
    // 3) y = att @ W_out + b_out
    gemm_bias_kernel<<<gemm_grid, 256>>>(p_att, W_out, b_out, p_y, NN, EMB, EMB);
    // 4) LayerNorm -> out
    ln_kernel<<<NN, 256>>>(gamma, beta, out);
}

// round 7
// speedup vs baseline: 2.3179x; 1.0722x over previous
#include <cuda_runtime.h>
#include <cuda_bf16.h>
#include <math.h>

#define NN  4096
#define EMB 256
#define NH  4
#define HC  64

typedef unsigned long long ull;

// ---- device scratch (no allocations allowed) ----
__device__ float    g_h[NN*EMB];
__device__ float    g_att[NN*EMB];
__device__ float    g_y[NN*EMB];
__device__ float    g_r[NH*NN];                 // e^{0.8 s_i}
__device__ float    g_ab[NH*NN*2];              // interleaved (e^{t_j}, e^{0.2 t_j})
__device__ unsigned g_adjbits[NN*(NN/32)];      // adjacency bitmask, diag=1
__device__ __nv_bfloat16 g_hThi[(size_t)NH*HC*NN];   // h transposed, bf16 hi (trunc)
__device__ __nv_bfloat16 g_hTlo[(size_t)NH*HC*NN];   // h transposed, bf16 lo (residual)

__device__ __forceinline__ unsigned swz(unsigned o) { return o ^ ((o >> 3) & 0x70); }

__device__ __forceinline__ void ldsm4(unsigned& r0, unsigned& r1, unsigned& r2, unsigned& r3,
                                      unsigned a) {
    asm volatile("ldmatrix.sync.aligned.m8n8.x4.shared.b16 {%0,%1,%2,%3}, [%4];"
        : "=r"(r0), "=r"(r1), "=r"(r2), "=r"(r3) : "r"(a));
}
__device__ __forceinline__ void mma16816(float* d, unsigned a0, unsigned a1, unsigned a2,
                                         unsigned a3, unsigned b0, unsigned b1) {
    asm volatile("mma.sync.aligned.m16n8k16.row.col.f32.bf16.bf16.f32 "
        "{%0,%1,%2,%3}, {%4,%5,%6,%7}, {%8,%9}, {%0,%1,%2,%3};"
        : "+f"(d[0]), "+f"(d[1]), "+f"(d[2]), "+f"(d[3])
        : "r"(a0), "r"(a1), "r"(a2), "r"(a3), "r"(b0), "r"(b1));
}
__device__ __forceinline__ void cpa16(unsigned dst, const void* src) {
    asm volatile("cp.async.cg.shared.global [%0], [%1], 16;" :: "r"(dst), "l"(src));
}

// ---------------------------------------------------------------------------
// fp32 GEMM, double-buffered k (one sync per chunk): Co = A@B (+bias). 64x64.
// ---------------------------------------------------------------------------
__global__ __launch_bounds__(256) void gemm_bias_kernel(
    const float* __restrict__ A, const float* __restrict__ B,
    const float* __restrict__ bias, float* __restrict__ Co,
    int M, int Nc, int K)
{
    __shared__ float as[2][16][68];
    __shared__ float bs[2][16][68];
    const int m0 = blockIdx.y * 64, n0 = blockIdx.x * 64;
    const int tid = threadIdx.x;
    const int ty = tid >> 4, tx = tid & 15;

    float acc[4][4];
#pragma unroll
    for (int i = 0; i < 4; i++)
#pragma unroll
        for (int j = 0; j < 4; j++) acc[i][j] = 0.f;

    int c = 0;
    for (int k0 = 0; k0 < K; k0 += 16, c ^= 1) {
        {
            int r = tid >> 2, c4 = tid & 3;
            float4 v = *(const float4*)&A[(m0 + r) * K + k0 + c4 * 4];
            as[c][c4*4+0][r] = v.x; as[c][c4*4+1][r] = v.y;
            as[c][c4*4+2][r] = v.z; as[c][c4*4+3][r] = v.w;
        }
        {
            int r = tid >> 4, c4 = tid & 15;
            *(float4*)&bs[c][r][c4*4] = *(const float4*)&B[(k0 + r) * Nc + n0 + c4 * 4];
        }
        __syncthreads();
#pragma unroll
        for (int k = 0; k < 16; k++) {
            float4 av = *(const float4*)&as[c][k][ty * 4];
            float4 bv = *(const float4*)&bs[c][k][tx * 4];
            float a4[4] = {av.x, av.y, av.z, av.w};
            float b4[4] = {bv.x, bv.y, bv.z, bv.w};
#pragma unroll
            for (int i = 0; i < 4; i++)
#pragma unroll
                for (int j = 0; j < 4; j++) acc[i][j] += a4[i] * b4[j];
        }
    }
#pragma unroll
    for (int i = 0; i < 4; i++) {
        int row = m0 + ty * 4 + i;
#pragma unroll
        for (int j = 0; j < 4; j++) {
            int col = n0 + tx * 4 + j;
            float v = acc[i][j];
            if (bias) v += bias[col];
            Co[row * Nc + col] = v;
        }
    }
}

// ---------------------------------------------------------------------------
// adj -> bitmask (forced self-loop)
// ---------------------------------------------------------------------------
__global__ __launch_bounds__(256) void adjbits_kernel(const int* __restrict__ adj)
{
    int row  = blockIdx.x;
    int lane = threadIdx.x & 31;
    int w    = threadIdx.x >> 5;
#pragma unroll
    for (int wd = w; wd < NN/32; wd += 8) {
        int v = adj[(long)row * NN + wd * 32 + lane];
        unsigned bits = __ballot_sync(0xffffffffu, v != 0);
        if ((row >> 5) == wd) bits |= 1u << (row & 31);
        if (lane == 0) g_adjbits[row * (NN/32) + wd] = bits;
    }
}

// ---------------------------------------------------------------------------
// Prep: per (head,node) r = e^{0.8s}, ab = (e^t, e^{0.2t})
// ---------------------------------------------------------------------------
__global__ __launch_bounds__(256) void prep_kernel(
    const float* __restrict__ att_src, const float* __restrict__ att_dst)
{
    int wid  = blockIdx.x * 8 + (threadIdx.x >> 5);
    int lane = threadIdx.x & 31;
    int hd = wid >> 12;
    int n  = wid & (NN - 1);
    const float* hp = g_h + n * EMB + hd * HC;
    float h0 = hp[lane], h1 = hp[lane + 32];
    float s = h0 * att_dst[hd*HC + lane] + h1 * att_dst[hd*HC + lane + 32];
    float t = h0 * att_src[hd*HC + lane] + h1 * att_src[hd*HC + lane + 32];
#pragma unroll
    for (int o = 16; o; o >>= 1) {
        s += __shfl_xor_sync(0xffffffffu, s, o);
        t += __shfl_xor_sync(0xffffffffu, t, o);
    }
    if (lane == 0) {
        g_r[wid] = expf(0.8f * s);
        g_ab[2*wid]   = expf(t);
        g_ab[2*wid+1] = expf(0.2f * t);
    }
}

// ---------------------------------------------------------------------------
// h -> transposed split-bf16: g_hThi/lo[hd][c][j]. Block: one head x 64 j.
// ---------------------------------------------------------------------------
__global__ __launch_bounds__(256) void ht_kernel()
{
    __shared__ float s[64][65];
    const int hd = blockIdx.y, jt = blockIdx.x * 64;
    const int t = threadIdx.x;
    {
        int r = t >> 2, cq = t & 3;
        const float4* src = (const float4*)(g_h + (size_t)(jt + r) * EMB + hd * HC + cq * 16);
#pragma unroll
        for (int u = 0; u < 4; u++) {
            float4 v = src[u];
            int cb = cq * 16 + u * 4;
            s[r][cb] = v.x; s[r][cb+1] = v.y; s[r][cb+2] = v.z; s[r][cb+3] = v.w;
        }
    }
    __syncthreads();
    int c = t >> 2, jq = t & 3;
    unsigned hi[8], lo[8];
#pragma unroll
    for (int e = 0; e < 8; e++) {
        float f0 = s[jq*16 + 2*e][c];
        float f1 = s[jq*16 + 2*e + 1][c];
        unsigned u0 = __float_as_uint(f0), u1 = __float_as_uint(f1);
        hi[e] = __byte_perm(u0, u1, 0x7632);
        float r0 = f0 - __uint_as_float(u0 & 0xffff0000u);
        float r1 = f1 - __uint_as_float(u1 & 0xffff0000u);
        asm("cvt.rn.bf16x2.f32 %0, %1, %2;" : "=r"(lo[e]) : "f"(r1), "f"(r0));
    }
    size_t o = (size_t)(hd * HC + c) * NN + jt + jq * 16;
    *(uint4*)(g_hThi + o)       = make_uint4(hi[0], hi[1], hi[2], hi[3]);
    *((uint4*)(g_hThi + o) + 1) = make_uint4(hi[4], hi[5], hi[6], hi[7]);
    *(uint4*)(g_hTlo + o)       = make_uint4(lo[0], lo[1], lo[2], lo[3]);
    *((uint4*)(g_hTlo + o) + 1) = make_uint4(lo[4], lo[5], lo[6], lo[7]);
}

// ---------------------------------------------------------------------------
// GAT aggregation via mma.sync bf16 (split hi/lo, 3 products).
// Block = 128 rows x 1 head, 256 threads (8 warps x 16 rows).
// Double-buffered smem tiles, ONE barrier per j-tile; cp.async B loads.
// ---------------------------------------------------------------------------
#define SM_AB   0         // 32768 B: (a,b) pairs for whole head
#define SM_A    32768     // 2 bufs x (hi 16384 + lo 16384)
#define SM_B    98304     // 2 bufs x (hi 8192 + lo 8192)
#define SM_D    131072    // 1024 B
#define SM_TOT  132096

__global__ __launch_bounds__(256) void gat_mma_kernel(const float* __restrict__ bias_att)
{
    extern __shared__ char smc[];
    const unsigned sb = (unsigned)__cvta_generic_to_shared(smc);
    const int tid  = threadIdx.x;
    const int hd   = blockIdx.y;
    const int i0   = blockIdx.x * 128;
    const int lane = tid & 31;
    const int warp = tid >> 5;
    const int m0   = warp * 16;

    // preload (a,b) pairs for this head into smem
    {
        const float4* src = (const float4*)(g_ab + (size_t)hd * NN * 2);
        float4* dst = (float4*)(smc + SM_AB);
        for (int k = tid; k < NN / 2; k += 256) dst[k] = src[k];
    }

    // phase-C mapping: 2 threads per dest row, 32 j each
    const int row  = tid >> 1;
    const int half = tid & 1;
    const float ri = g_r[hd * NN + i0 + row];
    const unsigned* abw = g_adjbits + (size_t)(i0 + row) * (NN / 32);
    const float4* abt4  = (const float4*)(smc + SM_AB);
    float dreg = 0.f;

    // mma fragment addressing constants
    const int grp = lane >> 3, lr = lane & 7;
    const unsigned arow = (unsigned)(m0 + lr + ((grp & 1) << 3));
    const unsigned khalf = (unsigned)((grp >> 1) << 4);

    const __nv_bfloat16* bhsrc0 = g_hThi + (size_t)hd * HC * NN;
    const __nv_bfloat16* blsrc0 = g_hTlo + (size_t)hd * HC * NN;

    float acc[8][4];
#pragma unroll
    for (int n = 0; n < 8; n++)
#pragma unroll
        for (int e = 0; e < 4; e++) acc[n][e] = 0.f;

    __syncthreads();   // ab ready

    for (int t = 0; t < 64; t++) {
        const int j0  = t * 64;
        const int buf = t & 1;
        const unsigned abase = SM_A + buf * 32768;   // hi @0, lo @+16384
        const unsigned bbase = SM_B + buf * 16384;   // hi @0, lo @+8192

        // B tiles via cp.async: hT [64 c][64 j] bf16 hi/lo, SW128
#pragma unroll
        for (int r = 0; r < 2; r++) {
            int ch = tid + r * 256;
            int cc = ch >> 3, q = ch & 7;
            unsigned so = swz((unsigned)(cc * 128 + q * 16));
            cpa16(sb + bbase + so,        bhsrc0 + (size_t)cc * NN + j0 + q * 8);
            cpa16(sb + bbase + 8192 + so, blsrc0 + (size_t)cc * NN + j0 + q * 8);
        }
        asm volatile("cp.async.commit_group;" ::: "memory");

        // A tile: c[row][j] masked weights, split bf16, 32 j per thread
        {
            char* Ahi = smc + abase;
            char* Alo = smc + abase + 16384;
            unsigned wb = abw[(j0 >> 5) + half];
            const float4* abt = abt4 + (j0 >> 1) + half * 16;
#pragma unroll
            for (int q = 0; q < 4; q++) {
                unsigned hi4[4], lo4[4];
#pragma unroll
                for (int p = 0; p < 4; p++) {
                    float4 v = abt[q * 4 + p];
                    int sh = q * 8 + p * 2;
                    float c0 = ((wb >> sh) & 1u)       ? fmaxf(ri * v.x, v.y) : 0.f;
                    float c1 = ((wb >> (sh + 1)) & 1u) ? fmaxf(ri * v.z, v.w) : 0.f;
                    dreg += c0 + c1;
                    unsigned u0 = __float_as_uint(c0), u1 = __float_as_uint(c1);
                    hi4[p] = __byte_perm(u0, u1, 0x7632);
                    float r0 = c0 - __uint_as_float(u0 & 0xffff0000u);
                    float r1 = c1 - __uint_as_float(u1 & 0xffff0000u);
                    asm("cvt.rn.bf16x2.f32 %0, %1, %2;" : "=r"(lo4[p]) : "f"(r1), "f"(r0));
                }
                unsigned so = swz((unsigned)(row * 128 + half * 64 + q * 16));
                *(uint4*)(Ahi + so) = make_uint4(hi4[0], hi4[1], hi4[2], hi4[3]);
                *(uint4*)(Alo + so) = make_uint4(lo4[0], lo4[1], lo4[2], lo4[3]);
            }
        }
        asm volatile("cp.async.wait_group 0;" ::: "memory");
        __syncthreads();   // tiles(buf) ready; prev tile's reads ordered before next writes

        // mma phase: warp owns rows [m0, m0+16)
#pragma unroll
        for (int kk = 0; kk < 4; kk++) {
            unsigned aoff = swz(arow * 128 + (unsigned)(kk * 32) + khalf);
            unsigned ah0, ah1, ah2, ah3, al0, al1, al2, al3;
            ldsm4(ah0, ah1, ah2, ah3, sb + abase + aoff);
            ldsm4(al0, al1, al2, al3, sb + abase + 16384 + aoff);
#pragma unroll
            for (int np = 0; np < 4; np++) {
                unsigned nrow = (unsigned)(np * 16 + lr + ((grp & 1) << 3));
                unsigned boff = swz(nrow * 128 + (unsigned)(kk * 32) + khalf);
                unsigned bh0, bh1, bh2, bh3, bl0, bl1, bl2, bl3;
                ldsm4(bh0, bh1, bh2, bh3, sb + bbase + boff);
                ldsm4(bl0, bl1, bl2, bl3, sb + bbase + 8192 + boff);
                mma16816(acc[2*np],   ah0, ah1, ah2, ah3, bh0, bh2);
                mma16816(acc[2*np],   ah0, ah1, ah2, ah3, bl0, bl2);
                mma16816(acc[2*np],   al0, al1, al2, al3, bh0, bh2);
                mma16816(acc[2*np+1], ah0, ah1, ah2, ah3, bh1, bh3);
                mma16816(acc[2*np+1], ah0, ah1, ah2, ah3, bl1, bl3);
                mma16816(acc[2*np+1], al0, al1, al2, al3, bh1, bh3);
            }
        }
    }

    // denominators
    ((float*)(smc + SM_D))[tid] = dreg;
    __syncthreads();

    // epilogue: rows m0 + lane/4 and +8; cols n*8 + (lane%4)*2
    {
        const float* dsm = (const float*)(smc + SM_D);
        int r0 = m0 + (lane >> 2);
        int r1 = r0 + 8;
        float inv0 = 1.0f / (dsm[2*r0] + dsm[2*r0 + 1]);
        float inv1 = 1.0f / (dsm[2*r1] + dsm[2*r1 + 1]);
        float* d0 = g_att + (size_t)(i0 + r0) * EMB + hd * HC;
        float* d1 = g_att + (size_t)(i0 + r1) * EMB + hd * HC;
        int cbase = (lane & 3) * 2;
#pragma unroll
        for (int nn = 0; nn < 8; nn++) {
            int col = nn * 8 + cbase;
            float b0 = __ldg(bias_att + hd * HC + col);
            float b1 = __ldg(bias_att + hd * HC + col + 1);
            *(float2*)(d0 + col) = make_float2(acc[nn][0] * inv0 + b0,
                                               acc[nn][1] * inv0 + b1);
            *(float2*)(d1 + col) = make_float2(acc[nn][2] * inv1 + b0,
                                               acc[nn][3] * inv1 + b1);
        }
    }
}

// ---------------------------------------------------------------------------
// LayerNorm over last dim (256), one block per row.
// ---------------------------------------------------------------------------
__global__ __launch_bounds__(256) void ln_kernel(
    const float* __restrict__ gamma, const float* __restrict__ beta,
    float* __restrict__ out)
{
    __shared__ float red1[8], red2[8];
    int row = blockIdx.x;
    int tid = threadIdx.x;
    float v = g_y[row * EMB + tid];

    float s = v;
#pragma unroll
    for (int o = 16; o; o >>= 1) s += __shfl_xor_sync(0xffffffffu, s, o);
    if ((tid & 31) == 0) red1[tid >> 5] = s;
    __syncthreads();
    float mu = 0.f;
#pragma unroll
    for (int k = 0; k < 8; k++) mu += red1[k];
    mu *= (1.0f / EMB);

    float d = v - mu;
    float q = d * d;
#pragma unroll
    for (int o = 16; o; o >>= 1) q += __shfl_xor_sync(0xffffffffu, q, o);
    if ((tid & 31) == 0) red2[tid >> 5] = q;
    __syncthreads();
    float var = 0.f;
#pragma unroll
    for (int k = 0; k < 8; k++) var += red2[k];
    var *= (1.0f / EMB);

    out[row * EMB + tid] = d * rsqrtf(var + 1e-5f) * gamma[tid] + beta[tid];
}

// ---------------------------------------------------------------------------
extern "C" void kernel_launch(void* const* d_in, const int* in_sizes, int n_in,
                              void* d_out, int out_size)
{
    const float* x        = (const float*)d_in[0];
    const int*   adj      = (const int*)  d_in[1];
    const float* W_lin    = (const float*)d_in[2];
    const float* att_src  = (const float*)d_in[3];
    const float* att_dst  = (const float*)d_in[4];
    const float* bias_att = (const float*)d_in[5];
    const float* W_out    = (const float*)d_in[6];
    const float* b_out    = (const float*)d_in[7];
    const float* gamma    = (const float*)d_in[8];
    const float* beta     = (const float*)d_in[9];
    float* out = (float*)d_out;

    float *p_h, *p_att, *p_y;
    cudaGetSymbolAddress((void**)&p_h,   g_h);
    cudaGetSymbolAddress((void**)&p_att, g_att);
    cudaGetSymbolAddress((void**)&p_y,   g_y);

    cudaFuncSetAttribute(gat_mma_kernel, cudaFuncAttributeMaxDynamicSharedMemorySize, SM_TOT);

    dim3 gemm_grid(EMB / 64, NN / 64);  // (4, 64)

    // 1) h = x @ W_lin
    gemm_bias_kernel<<<gemm_grid, 256>>>(x, W_lin, nullptr, p_h, NN, EMB, EMB);
    adjbits_kernel<<<NN, 256>>>(adj);
    prep_kernel<<<(NH * NN) / 8, 256>>>(att_src, att_dst);
    ht_kernel<<<dim3(NN / 64, NH), 256>>>();
    // 2) HMMA masked-softmax aggregation (+bias_att)
    gat_mma_kernel<<<dim3(NN / 128, NH), 256, SM_TOT>>>(bias_att);
    // 3) y = att @ W_out + b_out
    gemm_bias_kernel<<<gemm_grid, 256>>>(p_att, W_out, b_out, p_y, NN, EMB, EMB);
    // 4) LayerNorm -> out
    ln_kernel<<<NN, 256>>>(gamma, beta, out);
}

// round 8
// speedup vs baseline: 3.0063x; 1.2970x over previous
#include <cuda_runtime.h>
#include <cuda_bf16.h>
#include <cuda_fp16.h>
#include <math.h>

#define NN  4096
#define EMB 256
#define NH  4
#define HC  64

typedef unsigned long long ull;

// ---- device scratch (no allocations allowed) ----
__device__ float    g_h[NN*EMB];
__device__ float    g_y[NN*EMB];
__device__ float    g_r[NH*NN];                 // e^{0.8 s_i}
__device__ float    g_ab[NH*NN*2];              // interleaved (e^{t_j}, e^{0.2 t_j})
__device__ unsigned g_adjbits[NN*(NN/32)];      // adjacency bitmask, diag=1
__device__ __half   g_hThi[(size_t)NH*HC*NN];   // h transposed, fp16 hi
__device__ __half   g_hTlo[(size_t)NH*HC*NN];   // h transposed, fp16 lo (residual)
__device__ __nv_bfloat16 g_xhi[NN*EMB],  g_xlo[NN*EMB];    // x split (row-major)
__device__ __nv_bfloat16 g_atthi[NN*EMB], g_attlo[NN*EMB]; // att split (row-major)
__device__ __nv_bfloat16 g_wlhi[EMB*EMB], g_wllo[EMB*EMB]; // W_lin^T split [n][k]
__device__ __nv_bfloat16 g_wohi[EMB*EMB], g_wolo[EMB*EMB]; // W_out^T split [n][k]

__device__ __forceinline__ unsigned swz(unsigned o) { return o ^ ((o >> 3) & 0x70); }

__device__ __forceinline__ void ldsm4(unsigned& r0, unsigned& r1, unsigned& r2, unsigned& r3,
                                      unsigned a) {
    asm volatile("ldmatrix.sync.aligned.m8n8.x4.shared.b16 {%0,%1,%2,%3}, [%4];"
        : "=r"(r0), "=r"(r1), "=r"(r2), "=r"(r3) : "r"(a));
}
__device__ __forceinline__ void mma_bf(float* d, unsigned a0, unsigned a1, unsigned a2,
                                       unsigned a3, unsigned b0, unsigned b1) {
    asm volatile("mma.sync.aligned.m16n8k16.row.col.f32.bf16.bf16.f32 "
        "{%0,%1,%2,%3}, {%4,%5,%6,%7}, {%8,%9}, {%0,%1,%2,%3};"
        : "+f"(d[0]), "+f"(d[1]), "+f"(d[2]), "+f"(d[3])
        : "r"(a0), "r"(a1), "r"(a2), "r"(a3), "r"(b0), "r"(b1));
}
__device__ __forceinline__ void mma_h(float* d, unsigned a0, unsigned a1, unsigned a2,
                                      unsigned a3, unsigned b0, unsigned b1) {
    asm volatile("mma.sync.aligned.m16n8k16.row.col.f32.f16.f16.f32 "
        "{%0,%1,%2,%3}, {%4,%5,%6,%7}, {%8,%9}, {%0,%1,%2,%3};"
        : "+f"(d[0]), "+f"(d[1]), "+f"(d[2]), "+f"(d[3])
        : "r"(a0), "r"(a1), "r"(a2), "r"(a3), "r"(b0), "r"(b1));
}
__device__ __forceinline__ void cpa16(unsigned dst, const void* src) {
    asm volatile("cp.async.cg.shared.global [%0], [%1], 16;" :: "r"(dst), "l"(src));
}
__device__ __forceinline__ unsigned bfpairhi(float f0, float f1) {
    return __byte_perm(__float_as_uint(f0), __float_as_uint(f1), 0x7632);
}
__device__ __forceinline__ unsigned bfpairlo(float f0, float f1) {
    float r0 = f0 - __uint_as_float(__float_as_uint(f0) & 0xffff0000u);
    float r1 = f1 - __uint_as_float(__float_as_uint(f1) & 0xffff0000u);
    unsigned r; asm("cvt.rn.bf16x2.f32 %0, %1, %2;" : "=r"(r) : "f"(r1), "f"(r0));
    return r;
}

// ---------------------------------------------------------------------------
// Split x (row-major fp32) -> bf16 hi/lo, pairwise.
// ---------------------------------------------------------------------------
__global__ __launch_bounds__(256) void xsplit_kernel(const float* __restrict__ x)
{
    int i = blockIdx.x * 256 + threadIdx.x;          // pair index, grid 2048
    float2 v = ((const float2*)x)[i];
    ((unsigned*)g_xhi)[i] = bfpairhi(v.x, v.y);
    ((unsigned*)g_xlo)[i] = bfpairlo(v.x, v.y);
}

// ---------------------------------------------------------------------------
// Split + transpose W[k][n] -> whi/wlo [n][k] bf16.
// ---------------------------------------------------------------------------
__global__ __launch_bounds__(256) void wsplit_kernel(
    const float* __restrict__ W, __nv_bfloat16* __restrict__ whi,
    __nv_bfloat16* __restrict__ wlo)
{
    int idx = blockIdx.x * 256 + threadIdx.x;        // 0..32767, grid 128
    int n = idx >> 7, kp = (idx & 127) * 2;
    float f0 = W[kp * EMB + n], f1 = W[(kp + 1) * EMB + n];
    ((unsigned*)whi)[n * 128 + (kp >> 1)] = bfpairhi(f0, f1);
    ((unsigned*)wlo)[n * 128 + (kp >> 1)] = bfpairlo(f0, f1);
}

// ---------------------------------------------------------------------------
// Dense GEMM via mma.sync bf16 3-product: Co[M,256] = A[M,256]@B^T + bias.
// A: row-major bf16 hi/lo. B: [n][k] bf16 hi/lo. Block 128m x 64n, 8 warps.
// ---------------------------------------------------------------------------
#define GM_A 0        // 2 bufs x (hi 16K + lo 16K)
#define GM_B 65536    // 2 bufs x (hi 8K + lo 8K)
#define GM_TOT 98304

__global__ __launch_bounds__(256) void gemm_mma_kernel(
    const __nv_bfloat16* __restrict__ Ahi, const __nv_bfloat16* __restrict__ Alo,
    const __nv_bfloat16* __restrict__ Bhi, const __nv_bfloat16* __restrict__ Blo,
    const float* __restrict__ bias, float* __restrict__ Co)
{
    extern __shared__ char smc[];
    const unsigned sb = (unsigned)__cvta_generic_to_shared(smc);
    const int tid  = threadIdx.x;
    const int m0   = blockIdx.y * 128;
    const int n0   = blockIdx.x * 64;
    const int lane = tid & 31;
    const int warp = tid >> 5;
    const int grp  = lane >> 3, lr = lane & 7;
    const unsigned arow  = (unsigned)(warp * 16 + lr + ((grp & 1) << 3));
    const unsigned khalf = (unsigned)((grp >> 1) << 4);

    float acc[8][4];
#pragma unroll
    for (int n = 0; n < 8; n++)
#pragma unroll
        for (int e = 0; e < 4; e++) acc[n][e] = 0.f;

    for (int kc = 0; kc < 4; kc++) {
        const int buf = kc & 1;
        const unsigned ab = GM_A + buf * 32768;
        const unsigned bb = GM_B + buf * 16384;
        const int k0 = kc * 64;

        // A tile [128][64] hi/lo
#pragma unroll
        for (int r = 0; r < 4; r++) {
            int ch = tid + r * 256;
            int row = ch >> 3, q = ch & 7;
            unsigned so = swz((unsigned)(row * 128 + q * 16));
            size_t off = (size_t)(m0 + row) * EMB + k0 + q * 8;
            cpa16(sb + ab + so,         Ahi + off);
            cpa16(sb + ab + 16384 + so, Alo + off);
        }
        // B tile [64][64] hi/lo
#pragma unroll
        for (int r = 0; r < 2; r++) {
            int ch = tid + r * 256;
            int n = ch >> 3, q = ch & 7;
            unsigned so = swz((unsigned)(n * 128 + q * 16));
            size_t off = (size_t)(n0 + n) * EMB + k0 + q * 8;
            cpa16(sb + bb + so,        Bhi + off);
            cpa16(sb + bb + 8192 + so, Blo + off);
        }
        asm volatile("cp.async.commit_group;" ::: "memory");
        asm volatile("cp.async.wait_group 0;" ::: "memory");
        __syncthreads();

#pragma unroll
        for (int kk = 0; kk < 4; kk++) {
            unsigned aoff = swz(arow * 128 + (unsigned)(kk * 32) + khalf);
            unsigned ah0, ah1, ah2, ah3, al0, al1, al2, al3;
            ldsm4(ah0, ah1, ah2, ah3, sb + ab + aoff);
            ldsm4(al0, al1, al2, al3, sb + ab + 16384 + aoff);
#pragma unroll
            for (int np = 0; np < 4; np++) {
                unsigned nrow = (unsigned)(np * 16 + lr + ((grp & 1) << 3));
                unsigned boff = swz(nrow * 128 + (unsigned)(kk * 32) + khalf);
                unsigned bh0, bh1, bh2, bh3, bl0, bl1, bl2, bl3;
                ldsm4(bh0, bh1, bh2, bh3, sb + bb + boff);
                ldsm4(bl0, bl1, bl2, bl3, sb + bb + 8192 + boff);
                mma_bf(acc[2*np],   ah0, ah1, ah2, ah3, bh0, bh2);
                mma_bf(acc[2*np],   ah0, ah1, ah2, ah3, bl0, bl2);
                mma_bf(acc[2*np],   al0, al1, al2, al3, bh0, bh2);
                mma_bf(acc[2*np+1], ah0, ah1, ah2, ah3, bh1, bh3);
                mma_bf(acc[2*np+1], ah0, ah1, ah2, ah3, bl1, bl3);
                mma_bf(acc[2*np+1], al0, al1, al2, al3, bh1, bh3);
            }
        }
    }

    // epilogue
    int r0 = m0 + warp * 16 + (lane >> 2);
    int r1 = r0 + 8;
    int cb = (lane & 3) * 2;
#pragma unroll
    for (int nn = 0; nn < 8; nn++) {
        int col = n0 + nn * 8 + cb;
        float b0 = bias ? __ldg(bias + col)     : 0.f;
        float b1 = bias ? __ldg(bias + col + 1) : 0.f;
        *(float2*)&Co[(size_t)r0 * EMB + col] = make_float2(acc[nn][0] + b0, acc[nn][1] + b1);
        *(float2*)&Co[(size_t)r1 * EMB + col] = make_float2(acc[nn][2] + b0, acc[nn][3] + b1);
    }
}

// ---------------------------------------------------------------------------
// adj -> bitmask (forced self-loop)
// ---------------------------------------------------------------------------
__global__ __launch_bounds__(256) void adjbits_kernel(const int* __restrict__ adj)
{
    int row  = blockIdx.x;
    int lane = threadIdx.x & 31;
    int w    = threadIdx.x >> 5;
#pragma unroll
    for (int wd = w; wd < NN/32; wd += 8) {
        int v = adj[(long)row * NN + wd * 32 + lane];
        unsigned bits = __ballot_sync(0xffffffffu, v != 0);
        if ((row >> 5) == wd) bits |= 1u << (row & 31);
        if (lane == 0) g_adjbits[row * (NN/32) + wd] = bits;
    }
}

// ---------------------------------------------------------------------------
// Prep: per (head,node) r = e^{0.8s}, ab = (e^t, e^{0.2t})
// ---------------------------------------------------------------------------
__global__ __launch_bounds__(256) void prep_kernel(
    const float* __restrict__ att_src, const float* __restrict__ att_dst)
{
    int wid  = blockIdx.x * 8 + (threadIdx.x >> 5);
    int lane = threadIdx.x & 31;
    int hd = wid >> 12;
    int n  = wid & (NN - 1);
    const float* hp = g_h + n * EMB + hd * HC;
    float h0 = hp[lane], h1 = hp[lane + 32];
    float s = h0 * att_dst[hd*HC + lane] + h1 * att_dst[hd*HC + lane + 32];
    float t = h0 * att_src[hd*HC + lane] + h1 * att_src[hd*HC + lane + 32];
#pragma unroll
    for (int o = 16; o; o >>= 1) {
        s += __shfl_xor_sync(0xffffffffu, s, o);
        t += __shfl_xor_sync(0xffffffffu, t, o);
    }
    if (lane == 0) {
        g_r[wid] = expf(0.8f * s);
        g_ab[2*wid]   = expf(t);
        g_ab[2*wid+1] = expf(0.2f * t);
    }
}

// ---------------------------------------------------------------------------
// h -> transposed split-fp16: g_hThi/lo[hd][c][j]. Block: one head x 64 j.
// ---------------------------------------------------------------------------
__global__ __launch_bounds__(256) void ht_kernel()
{
    __shared__ float s[64][65];
    const int hd = blockIdx.y, jt = blockIdx.x * 64;
    const int t = threadIdx.x;
    {
        int r = t >> 2, cq = t & 3;
        const float4* src = (const float4*)(g_h + (size_t)(jt + r) * EMB + hd * HC + cq * 16);
#pragma unroll
        for (int u = 0; u < 4; u++) {
            float4 v = src[u];
            int cb = cq * 16 + u * 4;
            s[r][cb] = v.x; s[r][cb+1] = v.y; s[r][cb+2] = v.z; s[r][cb+3] = v.w;
        }
    }
    __syncthreads();
    int c = t >> 2, jq = t & 3;
    unsigned hi[8], lo[8];
#pragma unroll
    for (int e = 0; e < 8; e++) {
        float f0 = s[jq*16 + 2*e][c];
        float f1 = s[jq*16 + 2*e + 1][c];
        __half2 hp = __floats2half2_rn(f0, f1);
        float r0 = f0 - __low2float(hp);
        float r1 = f1 - __high2float(hp);
        __half2 lp = __floats2half2_rn(r0, r1);
        hi[e] = *(unsigned*)&hp;
        lo[e] = *(unsigned*)&lp;
    }
    size_t o = (size_t)(hd * HC + c) * NN + jt + jq * 16;
    *(uint4*)(g_hThi + o)       = make_uint4(hi[0], hi[1], hi[2], hi[3]);
    *((uint4*)(g_hThi + o) + 1) = make_uint4(hi[4], hi[5], hi[6], hi[7]);
    *(uint4*)(g_hTlo + o)       = make_uint4(lo[0], lo[1], lo[2], lo[3]);
    *((uint4*)(g_hTlo + o) + 1) = make_uint4(lo[4], lo[5], lo[6], lo[7]);
}

// ---------------------------------------------------------------------------
// GAT aggregation via mma.sync fp16, 2 products (A single, B split hi/lo).
// Weights pre-scaled by 1/16 (cancels in softmax ratio) for fp16 range.
// Block = 128 rows x 1 head, 256 threads; double-buffered, 1 barrier/tile.
// Epilogue writes att split to bf16 hi/lo (feeds gemm2 directly).
// ---------------------------------------------------------------------------
#define SM_AB   0         // 32768 B
#define SM_A    32768     // 2 bufs x 16384 (fp16 c, hi only)
#define SM_B    65536     // 2 bufs x (hi 8192 + lo 8192)
#define SM_D    98304     // 1024 B
#define SM_TOT  99328

__global__ __launch_bounds__(256) void gat_mma_kernel(const float* __restrict__ bias_att)
{
    extern __shared__ char smc[];
    const unsigned sb = (unsigned)__cvta_generic_to_shared(smc);
    const int tid  = threadIdx.x;
    const int hd   = blockIdx.y;
    const int i0   = blockIdx.x * 128;
    const int lane = tid & 31;
    const int warp = tid >> 5;
    const int m0   = warp * 16;

    {
        const float4* src = (const float4*)(g_ab + (size_t)hd * NN * 2);
        float4* dst = (float4*)(smc + SM_AB);
        for (int k = tid; k < NN / 2; k += 256) dst[k] = src[k];
    }

    const int row  = tid >> 1;
    const int half = tid & 1;
    const float ri = g_r[hd * NN + i0 + row] * 0.0625f;   // fold 1/16 scale into ri
    const unsigned* abw = g_adjbits + (size_t)(i0 + row) * (NN / 32);
    const float4* abt4  = (const float4*)(smc + SM_AB);
    float dreg = 0.f;

    const int grp = lane >> 3, lr = lane & 7;
    const unsigned arow  = (unsigned)(m0 + lr + ((grp & 1) << 3));
    const unsigned khalf = (unsigned)((grp >> 1) << 4);

    const __half* bhsrc0 = g_hThi + (size_t)hd * HC * NN;
    const __half* blsrc0 = g_hTlo + (size_t)hd * HC * NN;

    float acc[8][4];
#pragma unroll
    for (int n = 0; n < 8; n++)
#pragma unroll
        for (int e = 0; e < 4; e++) acc[n][e] = 0.f;

    __syncthreads();   // ab ready

    for (int t = 0; t < 64; t++) {
        const int j0  = t * 64;
        const int buf = t & 1;
        const unsigned abase = SM_A + buf * 16384;
        const unsigned bbase = SM_B + buf * 16384;

        // B tiles via cp.async: hT [64 c][64 j] fp16 hi/lo, SW128
#pragma unroll
        for (int r = 0; r < 2; r++) {
            int ch = tid + r * 256;
            int cc = ch >> 3, q = ch & 7;
            unsigned so = swz((unsigned)(cc * 128 + q * 16));
            cpa16(sb + bbase + so,        bhsrc0 + (size_t)cc * NN + j0 + q * 8);
            cpa16(sb + bbase + 8192 + so, blsrc0 + (size_t)cc * NN + j0 + q * 8);
        }
        asm volatile("cp.async.commit_group;" ::: "memory");

        // A tile: scaled masked weights -> fp16, 32 j per thread
        {
            unsigned wb = abw[(j0 >> 5) + half];
            const float4* abt = abt4 + (j0 >> 1) + half * 16;
            // b values need the same 1/16 scale: ri pre-scaled covers ri*a term;
            // scale b explicitly.
#pragma unroll
            for (int q = 0; q < 4; q++) {
                unsigned hp4[4];
#pragma unroll
                for (int p = 0; p < 4; p++) {
                    float4 v = abt[q * 4 + p];
                    int sh = q * 8 + p * 2;
                    float c0 = ((wb >> sh) & 1u)       ? fmaxf(ri * v.x, 0.0625f * v.y) : 0.f;
                    float c1 = ((wb >> (sh + 1)) & 1u) ? fmaxf(ri * v.z, 0.0625f * v.w) : 0.f;
                    dreg += c0 + c1;
                    __half2 hh = __floats2half2_rn(c0, c1);
                    hp4[p] = *(unsigned*)&hh;
                }
                unsigned so = swz((unsigned)(row * 128 + half * 64 + q * 16));
                *(uint4*)(smc + abase + so) = make_uint4(hp4[0], hp4[1], hp4[2], hp4[3]);
            }
        }
        asm volatile("cp.async.wait_group 0;" ::: "memory");
        __syncthreads();

#pragma unroll
        for (int kk = 0; kk < 4; kk++) {
            unsigned aoff = swz(arow * 128 + (unsigned)(kk * 32) + khalf);
            unsigned a0, a1, a2, a3;
            ldsm4(a0, a1, a2, a3, sb + abase + aoff);
#pragma unroll
            for (int np = 0; np < 4; np++) {
                unsigned nrow = (unsigned)(np * 16 + lr + ((grp & 1) << 3));
                unsigned boff = swz(nrow * 128 + (unsigned)(kk * 32) + khalf);
                unsigned bh0, bh1, bh2, bh3, bl0, bl1, bl2, bl3;
                ldsm4(bh0, bh1, bh2, bh3, sb + bbase + boff);
                ldsm4(bl0, bl1, bl2, bl3, sb + bbase + 8192 + boff);
                mma_h(acc[2*np],   a0, a1, a2, a3, bh0, bh2);
                mma_h(acc[2*np],   a0, a1, a2, a3, bl0, bl2);
                mma_h(acc[2*np+1], a0, a1, a2, a3, bh1, bh3);
                mma_h(acc[2*np+1], a0, a1, a2, a3, bl1, bl3);
            }
        }
    }

    ((float*)(smc + SM_D))[tid] = dreg;
    __syncthreads();

    // epilogue: normalize, +bias, split to bf16 hi/lo for gemm2
    {
        const float* dsm = (const float*)(smc + SM_D);
        int r0 = m0 + (lane >> 2);
        int r1 = r0 + 8;
        float inv0 = 1.0f / (dsm[2*r0] + dsm[2*r0 + 1]);
        float inv1 = 1.0f / (dsm[2*r1] + dsm[2*r1 + 1]);
        int cb = (lane & 3) * 2;
#pragma unroll
        for (int nn = 0; nn < 8; nn++) {
            int col = nn * 8 + cb;
            float b0 = __ldg(bias_att + hd * HC + col);
            float b1 = __ldg(bias_att + hd * HC + col + 1);
            float v00 = acc[nn][0] * inv0 + b0, v01 = acc[nn][1] * inv0 + b1;
            float v10 = acc[nn][2] * inv1 + b0, v11 = acc[nn][3] * inv1 + b1;
            size_t o0 = ((size_t)(i0 + r0) * EMB + hd * HC + col) >> 1;
            size_t o1 = ((size_t)(i0 + r1) * EMB + hd * HC + col) >> 1;
            ((unsigned*)g_atthi)[o0] = bfpairhi(v00, v01);
            ((unsigned*)g_attlo)[o0] = bfpairlo(v00, v01);
            ((unsigned*)g_atthi)[o1] = bfpairhi(v10, v11);
            ((unsigned*)g_attlo)[o1] = bfpairlo(v10, v11);
        }
    }
}

// ---------------------------------------------------------------------------
// LayerNorm over last dim (256), one block per row.
// ---------------------------------------------------------------------------
__global__ __launch_bounds__(256) void ln_kernel(
    const float* __restrict__ gamma, const float* __restrict__ beta,
    float* __restrict__ out)
{
    __shared__ float red1[8], red2[8];
    int row = blockIdx.x;
    int tid = threadIdx.x;
    float v = g_y[row * EMB + tid];

    float s = v;
#pragma unroll
    for (int o = 16; o; o >>= 1) s += __shfl_xor_sync(0xffffffffu, s, o);
    if ((tid & 31) == 0) red1[tid >> 5] = s;
    __syncthreads();
    float mu = 0.f;
#pragma unroll
    for (int k = 0; k < 8; k++) mu += red1[k];
    mu *= (1.0f / EMB);

    float d = v - mu;
    float q = d * d;
#pragma unroll
    for (int o = 16; o; o >>= 1) q += __shfl_xor_sync(0xffffffffu, q, o);
    if ((tid & 31) == 0) red2[tid >> 5] = q;
    __syncthreads();
    float var = 0.f;
#pragma unroll
    for (int k = 0; k < 8; k++) var += red2[k];
    var *= (1.0f / EMB);

    out[row * EMB + tid] = d * rsqrtf(var + 1e-5f) * gamma[tid] + beta[tid];
}

// ---------------------------------------------------------------------------
extern "C" void kernel_launch(void* const* d_in, const int* in_sizes, int n_in,
                              void* d_out, int out_size)
{
    const float* x        = (const float*)d_in[0];
    const int*   adj      = (const int*)  d_in[1];
    const float* W_lin    = (const float*)d_in[2];
    const float* att_src  = (const float*)d_in[3];
    const float* att_dst  = (const float*)d_in[4];
    const float* bias_att = (const float*)d_in[5];
    const float* W_out    = (const float*)d_in[6];
    const float* b_out    = (const float*)d_in[7];
    const float* gamma    = (const float*)d_in[8];
    const float* beta     = (const float*)d_in[9];
    float* out = (float*)d_out;

    float *p_h, *p_y;
    cudaGetSymbolAddress((void**)&p_h, g_h);
    cudaGetSymbolAddress((void**)&p_y, g_y);
    __nv_bfloat16 *p_xhi, *p_xlo, *p_athi, *p_atlo, *p_wlhi, *p_wllo, *p_wohi, *p_wolo;
    cudaGetSymbolAddress((void**)&p_xhi,  g_xhi);
    cudaGetSymbolAddress((void**)&p_xlo,  g_xlo);
    cudaGetSymbolAddress((void**)&p_athi, g_atthi);
    cudaGetSymbolAddress((void**)&p_atlo, g_attlo);
    cudaGetSymbolAddress((void**)&p_wlhi, g_wlhi);
    cudaGetSymbolAddress((void**)&p_wllo, g_wllo);
    cudaGetSymbolAddress((void**)&p_wohi, g_wohi);
    cudaGetSymbolAddress((void**)&p_wolo, g_wolo);

    cudaFuncSetAttribute(gat_mma_kernel,  cudaFuncAttributeMaxDynamicSharedMemorySize, SM_TOT);
    cudaFuncSetAttribute(gemm_mma_kernel, cudaFuncAttributeMaxDynamicSharedMemorySize, GM_TOT);

    dim3 gemm_grid(EMB / 64, NN / 128);  // (4, 32) = 128 blocks

    // splits
    wsplit_kernel<<<128, 256>>>(W_lin, p_wlhi, p_wllo);
    wsplit_kernel<<<128, 256>>>(W_out, p_wohi, p_wolo);
    xsplit_kernel<<<2048, 256>>>(x);
    // 1) h = x @ W_lin  (bf16 3-product mma)
    gemm_mma_kernel<<<gemm_grid, 256, GM_TOT>>>(p_xhi, p_xlo, p_wlhi, p_wllo, nullptr, p_h);
    adjbits_kernel<<<NN, 256>>>(adj);
    prep_kernel<<<(NH * NN) / 8, 256>>>(att_src, att_dst);
    ht_kernel<<<dim3(NN / 64, NH), 256>>>();
    // 2) fp16 2-product masked-softmax aggregation (+bias_att) -> att hi/lo
    gat_mma_kernel<<<dim3(NN / 128, NH), 256, SM_TOT>>>(bias_att);
    // 3) y = att @ W_out + b_out  (bf16 3-product mma)
    gemm_mma_kernel<<<gemm_grid, 256, GM_TOT>>>(p_athi, p_atlo, p_wohi, p_wolo, b_out, p_y);
    // 4) LayerNorm -> out
    ln_kernel<<<NN, 256>>>(gamma, beta, out);
}

// round 9
// speedup vs baseline: 3.9954x; 1.3290x over previous
#include <cuda_runtime.h>
#include <cuda_bf16.h>
#include <cuda_fp16.h>
#include <math.h>

#define NN  4096
#define EMB 256
#define NH  4
#define HC  64

typedef unsigned long long ull;

// ---- device scratch (no allocations allowed) ----
__device__ float    g_h[NN*EMB];
__device__ float    g_y[NN*EMB];
__device__ float    g_r[NH*NN];                 // e^{0.8 s_i}
__device__ float    g_ab[NH*NN*2];              // interleaved (e^{t_j}, e^{0.2 t_j})
__device__ unsigned g_adjbits[NN*(NN/32)];      // adjacency bitmask, diag=1
__device__ __half   g_hT[(size_t)NH*HC*NN];     // h transposed, fp16 (rn)
__device__ __nv_bfloat16 g_xhi[NN*EMB],  g_xlo[NN*EMB];    // x split (row-major)
__device__ __nv_bfloat16 g_atthi[NN*EMB], g_attlo[NN*EMB]; // att split (row-major)
__device__ __nv_bfloat16 g_wlhi[EMB*EMB], g_wllo[EMB*EMB]; // W_lin^T split [n][k]
__device__ __nv_bfloat16 g_wohi[EMB*EMB], g_wolo[EMB*EMB]; // W_out^T split [n][k]

__device__ __forceinline__ unsigned swz(unsigned o) { return o ^ ((o >> 3) & 0x70); }

__device__ __forceinline__ void ldsm4(unsigned& r0, unsigned& r1, unsigned& r2, unsigned& r3,
                                      unsigned a) {
    asm volatile("ldmatrix.sync.aligned.m8n8.x4.shared.b16 {%0,%1,%2,%3}, [%4];"
        : "=r"(r0), "=r"(r1), "=r"(r2), "=r"(r3) : "r"(a));
}
__device__ __forceinline__ void mma_bf(float* d, unsigned a0, unsigned a1, unsigned a2,
                                       unsigned a3, unsigned b0, unsigned b1) {
    asm volatile("mma.sync.aligned.m16n8k16.row.col.f32.bf16.bf16.f32 "
        "{%0,%1,%2,%3}, {%4,%5,%6,%7}, {%8,%9}, {%0,%1,%2,%3};"
        : "+f"(d[0]), "+f"(d[1]), "+f"(d[2]), "+f"(d[3])
        : "r"(a0), "r"(a1), "r"(a2), "r"(a3), "r"(b0), "r"(b1));
}
__device__ __forceinline__ void mma_h(float* d, unsigned a0, unsigned a1, unsigned a2,
                                      unsigned a3, unsigned b0, unsigned b1) {
    asm volatile("mma.sync.aligned.m16n8k16.row.col.f32.f16.f16.f32 "
        "{%0,%1,%2,%3}, {%4,%5,%6,%7}, {%8,%9}, {%0,%1,%2,%3};"
        : "+f"(d[0]), "+f"(d[1]), "+f"(d[2]), "+f"(d[3])
        : "r"(a0), "r"(a1), "r"(a2), "r"(a3), "r"(b0), "r"(b1));
}
__device__ __forceinline__ void cpa16(unsigned dst, const void* src) {
    asm volatile("cp.async.cg.shared.global [%0], [%1], 16;" :: "r"(dst), "l"(src));
}
__device__ __forceinline__ unsigned bfpairhi(float f0, float f1) {
    return __byte_perm(__float_as_uint(f0), __float_as_uint(f1), 0x7632);
}
__device__ __forceinline__ unsigned bfpairlo(float f0, float f1) {
    float r0 = f0 - __uint_as_float(__float_as_uint(f0) & 0xffff0000u);
    float r1 = f1 - __uint_as_float(__float_as_uint(f1) & 0xffff0000u);
    unsigned r; asm("cvt.rn.bf16x2.f32 %0, %1, %2;" : "=r"(r) : "f"(r1), "f"(r0));
    return r;
}

// ---------------------------------------------------------------------------
// Split x (row-major fp32) -> bf16 hi/lo, pairwise.
// ---------------------------------------------------------------------------
__global__ __launch_bounds__(256) void xsplit_kernel(const float* __restrict__ x)
{
    int i = blockIdx.x * 256 + threadIdx.x;          // pair index, grid 2048
    float2 v = ((const float2*)x)[i];
    ((unsigned*)g_xhi)[i] = bfpairhi(v.x, v.y);
    ((unsigned*)g_xlo)[i] = bfpairlo(v.x, v.y);
}

// ---------------------------------------------------------------------------
// Split + transpose W[k][n] -> whi/wlo [n][k] bf16.
// ---------------------------------------------------------------------------
__global__ __launch_bounds__(256) void wsplit_kernel(
    const float* __restrict__ W, __nv_bfloat16* __restrict__ whi,
    __nv_bfloat16* __restrict__ wlo)
{
    int idx = blockIdx.x * 256 + threadIdx.x;        // 0..32767, grid 128
    int n = idx >> 7, kp = (idx & 127) * 2;
    float f0 = W[kp * EMB + n], f1 = W[(kp + 1) * EMB + n];
    ((unsigned*)whi)[n * 128 + (kp >> 1)] = bfpairhi(f0, f1);
    ((unsigned*)wlo)[n * 128 + (kp >> 1)] = bfpairlo(f0, f1);
}

// ---------------------------------------------------------------------------
// Dense GEMM via mma.sync bf16 3-product, 2-stage cp.async pipeline.
// Co[M,256] = A[M,256]@B^T + bias. Block 128m x 64n, 8 warps.
// ---------------------------------------------------------------------------
#define GM_A 0        // 2 bufs x (hi 16K + lo 16K)
#define GM_B 65536    // 2 bufs x (hi 8K + lo 8K)
#define GM_TOT 98304

__global__ __launch_bounds__(256) void gemm_mma_kernel(
    const __nv_bfloat16* __restrict__ Ahi, const __nv_bfloat16* __restrict__ Alo,
    const __nv_bfloat16* __restrict__ Bhi, const __nv_bfloat16* __restrict__ Blo,
    const float* __restrict__ bias, float* __restrict__ Co)
{
    extern __shared__ char smc[];
    const unsigned sb = (unsigned)__cvta_generic_to_shared(smc);
    const int tid  = threadIdx.x;
    const int m0   = blockIdx.y * 128;
    const int n0   = blockIdx.x * 64;
    const int lane = tid & 31;
    const int warp = tid >> 5;
    const int grp  = lane >> 3, lr = lane & 7;
    const unsigned arow  = (unsigned)(warp * 16 + lr + ((grp & 1) << 3));
    const unsigned khalf = (unsigned)((grp >> 1) << 4);

    float acc[8][4];
#pragma unroll
    for (int n = 0; n < 8; n++)
#pragma unroll
        for (int e = 0; e < 4; e++) acc[n][e] = 0.f;

    auto load_chunk = [&](int kc, int buf) {
        const unsigned ab = GM_A + buf * 32768;
        const unsigned bb = GM_B + buf * 16384;
        const int k0 = kc * 64;
#pragma unroll
        for (int r = 0; r < 4; r++) {
            int ch = tid + r * 256;
            int row = ch >> 3, q = ch & 7;
            unsigned so = swz((unsigned)(row * 128 + q * 16));
            size_t off = (size_t)(m0 + row) * EMB + k0 + q * 8;
            cpa16(sb + ab + so,         Ahi + off);
            cpa16(sb + ab + 16384 + so, Alo + off);
        }
#pragma unroll
        for (int r = 0; r < 2; r++) {
            int ch = tid + r * 256;
            int n = ch >> 3, q = ch & 7;
            unsigned so = swz((unsigned)(n * 128 + q * 16));
            size_t off = (size_t)(n0 + n) * EMB + k0 + q * 8;
            cpa16(sb + bb + so,        Bhi + off);
            cpa16(sb + bb + 8192 + so, Blo + off);
        }
        asm volatile("cp.async.commit_group;" ::: "memory");
    };

    load_chunk(0, 0);
    for (int kc = 0; kc < 4; kc++) {
        const int buf = kc & 1;
        __syncthreads();                       // prior mma reads of buf^1 complete
        if (kc < 3) load_chunk(kc + 1, buf ^ 1);
        if (kc < 3) { asm volatile("cp.async.wait_group 1;" ::: "memory"); }
        else        { asm volatile("cp.async.wait_group 0;" ::: "memory"); }
        __syncthreads();                       // chunk kc visible to all

        const unsigned ab = GM_A + buf * 32768;
        const unsigned bb = GM_B + buf * 16384;
#pragma unroll
        for (int kk = 0; kk < 4; kk++) {
            unsigned aoff = swz(arow * 128 + (unsigned)(kk * 32) + khalf);
            unsigned ah0, ah1, ah2, ah3, al0, al1, al2, al3;
            ldsm4(ah0, ah1, ah2, ah3, sb + ab + aoff);
            ldsm4(al0, al1, al2, al3, sb + ab + 16384 + aoff);
#pragma unroll
            for (int np = 0; np < 4; np++) {
                unsigned nrow = (unsigned)(np * 16 + lr + ((grp & 1) << 3));
                unsigned boff = swz(nrow * 128 + (unsigned)(kk * 32) + khalf);
                unsigned bh0, bh1, bh2, bh3, bl0, bl1, bl2, bl3;
                ldsm4(bh0, bh1, bh2, bh3, sb + bb + boff);
                ldsm4(bl0, bl1, bl2, bl3, sb + bb + 8192 + boff);
                mma_bf(acc[2*np],   ah0, ah1, ah2, ah3, bh0, bh2);
                mma_bf(acc[2*np],   ah0, ah1, ah2, ah3, bl0, bl2);
                mma_bf(acc[2*np],   al0, al1, al2, al3, bh0, bh2);
                mma_bf(acc[2*np+1], ah0, ah1, ah2, ah3, bh1, bh3);
                mma_bf(acc[2*np+1], ah0, ah1, ah2, ah3, bl1, bl3);
                mma_bf(acc[2*np+1], al0, al1, al2, al3, bh1, bh3);
            }
        }
    }

    int r0 = m0 + warp * 16 + (lane >> 2);
    int r1 = r0 + 8;
    int cb = (lane & 3) * 2;
#pragma unroll
    for (int nn = 0; nn < 8; nn++) {
        int col = n0 + nn * 8 + cb;
        float b0 = bias ? __ldg(bias + col)     : 0.f;
        float b1 = bias ? __ldg(bias + col + 1) : 0.f;
        *(float2*)&Co[(size_t)r0 * EMB + col] = make_float2(acc[nn][0] + b0, acc[nn][1] + b1);
        *(float2*)&Co[(size_t)r1 * EMB + col] = make_float2(acc[nn][2] + b0, acc[nn][3] + b1);
    }
}

// ---------------------------------------------------------------------------
// adj -> bitmask (forced self-loop)
// ---------------------------------------------------------------------------
__global__ __launch_bounds__(256) void adjbits_kernel(const int* __restrict__ adj)
{
    int row  = blockIdx.x;
    int lane = threadIdx.x & 31;
    int w    = threadIdx.x >> 5;
#pragma unroll
    for (int wd = w; wd < NN/32; wd += 8) {
        int v = adj[(long)row * NN + wd * 32 + lane];
        unsigned bits = __ballot_sync(0xffffffffu, v != 0);
        if ((row >> 5) == wd) bits |= 1u << (row & 31);
        if (lane == 0) g_adjbits[row * (NN/32) + wd] = bits;
    }
}

// ---------------------------------------------------------------------------
// Prep: per (head,node) r = e^{0.8s}, ab = (e^t, e^{0.2t})
// ---------------------------------------------------------------------------
__global__ __launch_bounds__(256) void prep_kernel(
    const float* __restrict__ att_src, const float* __restrict__ att_dst)
{
    int wid  = blockIdx.x * 8 + (threadIdx.x >> 5);
    int lane = threadIdx.x & 31;
    int hd = wid >> 12;
    int n  = wid & (NN - 1);
    const float* hp = g_h + n * EMB + hd * HC;
    float h0 = hp[lane], h1 = hp[lane + 32];
    float s = h0 * att_dst[hd*HC + lane] + h1 * att_dst[hd*HC + lane + 32];
    float t = h0 * att_src[hd*HC + lane] + h1 * att_src[hd*HC + lane + 32];
#pragma unroll
    for (int o = 16; o; o >>= 1) {
        s += __shfl_xor_sync(0xffffffffu, s, o);
        t += __shfl_xor_sync(0xffffffffu, t, o);
    }
    if (lane == 0) {
        g_r[wid] = expf(0.8f * s);
        g_ab[2*wid]   = expf(t);
        g_ab[2*wid+1] = expf(0.2f * t);
    }
}

// ---------------------------------------------------------------------------
// h -> transposed fp16 (rn): g_hT[hd][c][j]. Block: one head x 64 j.
// ---------------------------------------------------------------------------
__global__ __launch_bounds__(256) void ht_kernel()
{
    __shared__ float s[64][65];
    const int hd = blockIdx.y, jt = blockIdx.x * 64;
    const int t = threadIdx.x;
    {
        int r = t >> 2, cq = t & 3;
        const float4* src = (const float4*)(g_h + (size_t)(jt + r) * EMB + hd * HC + cq * 16);
#pragma unroll
        for (int u = 0; u < 4; u++) {
            float4 v = src[u];
            int cb = cq * 16 + u * 4;
            s[r][cb] = v.x; s[r][cb+1] = v.y; s[r][cb+2] = v.z; s[r][cb+3] = v.w;
        }
    }
    __syncthreads();
    int c = t >> 2, jq = t & 3;
    unsigned hi[8];
#pragma unroll
    for (int e = 0; e < 8; e++) {
        __half2 hp = __floats2half2_rn(s[jq*16 + 2*e][c], s[jq*16 + 2*e + 1][c]);
        hi[e] = *(unsigned*)&hp;
    }
    size_t o = (size_t)(hd * HC + c) * NN + jt + jq * 16;
    *(uint4*)(g_hT + o)       = make_uint4(hi[0], hi[1], hi[2], hi[3]);
    *((uint4*)(g_hT + o) + 1) = make_uint4(hi[4], hi[5], hi[6], hi[7]);
}

// ---------------------------------------------------------------------------
// GAT aggregation via mma.sync fp16, SINGLE product (A fp16, B fp16 rn).
// Weights pre-scaled by 1/16 (cancels in softmax ratio) for fp16 range.
// Block = 128 rows x 1 head, 256 threads; double-buffered, 1 barrier/tile.
// Epilogue writes att split to bf16 hi/lo (feeds gemm2 directly).
// ---------------------------------------------------------------------------
#define SM_AB   0         // 32768 B
#define SM_A    32768     // 2 bufs x 16384 (fp16 c)
#define SM_B    65536     // 2 bufs x 8192 (fp16 hT)
#define SM_D    81920     // 1024 B
#define SM_TOT  82944

__global__ __launch_bounds__(256) void gat_mma_kernel(const float* __restrict__ bias_att)
{
    extern __shared__ char smc[];
    const unsigned sb = (unsigned)__cvta_generic_to_shared(smc);
    const int tid  = threadIdx.x;
    const int hd   = blockIdx.y;
    const int i0   = blockIdx.x * 128;
    const int lane = tid & 31;
    const int warp = tid >> 5;
    const int m0   = warp * 16;

    {
        const float4* src = (const float4*)(g_ab + (size_t)hd * NN * 2);
        float4* dst = (float4*)(smc + SM_AB);
        for (int k = tid; k < NN / 2; k += 256) dst[k] = src[k];
    }

    const int row  = tid >> 1;
    const int half = tid & 1;
    const float ri = g_r[hd * NN + i0 + row] * 0.0625f;   // fold 1/16 into ri
    const unsigned* abw = g_adjbits + (size_t)(i0 + row) * (NN / 32);
    const float4* abt4  = (const float4*)(smc + SM_AB);
    float dreg = 0.f;

    const int grp = lane >> 3, lr = lane & 7;
    const unsigned arow  = (unsigned)(m0 + lr + ((grp & 1) << 3));
    const unsigned khalf = (unsigned)((grp >> 1) << 4);

    const __half* bsrc0 = g_hT + (size_t)hd * HC * NN;

    float acc[8][4];
#pragma unroll
    for (int n = 0; n < 8; n++)
#pragma unroll
        for (int e = 0; e < 4; e++) acc[n][e] = 0.f;

    __syncthreads();   // ab ready

    for (int t = 0; t < 64; t++) {
        const int j0  = t * 64;
        const int buf = t & 1;
        const unsigned abase = SM_A + buf * 16384;
        const unsigned bbase = SM_B + buf * 8192;

        // B tile via cp.async: hT [64 c][64 j] fp16, SW128
#pragma unroll
        for (int r = 0; r < 2; r++) {
            int ch = tid + r * 256;
            int cc = ch >> 3, q = ch & 7;
            unsigned so = swz((unsigned)(cc * 128 + q * 16));
            cpa16(sb + bbase + so, bsrc0 + (size_t)cc * NN + j0 + q * 8);
        }
        asm volatile("cp.async.commit_group;" ::: "memory");

        // A tile: scaled masked weights -> fp16, 32 j per thread
        {
            unsigned wb = abw[(j0 >> 5) + half];
            const float4* abt = abt4 + (j0 >> 1) + half * 16;
#pragma unroll
            for (int q = 0; q < 4; q++) {
                unsigned hp4[4];
#pragma unroll
                for (int p = 0; p < 4; p++) {
                    float4 v = abt[q * 4 + p];
                    int sh = q * 8 + p * 2;
                    float c0 = ((wb >> sh) & 1u)       ? fmaxf(ri * v.x, 0.0625f * v.y) : 0.f;
                    float c1 = ((wb >> (sh + 1)) & 1u) ? fmaxf(ri * v.z, 0.0625f * v.w) : 0.f;
                    dreg += c0 + c1;
                    __half2 hh = __floats2half2_rn(c0, c1);
                    hp4[p] = *(unsigned*)&hh;
                }
                unsigned so = swz((unsigned)(row * 128 + half * 64 + q * 16));
                *(uint4*)(smc + abase + so) = make_uint4(hp4[0], hp4[1], hp4[2], hp4[3]);
            }
        }
        asm volatile("cp.async.wait_group 0;" ::: "memory");
        __syncthreads();

#pragma unroll
        for (int kk = 0; kk < 4; kk++) {
            unsigned aoff = swz(arow * 128 + (unsigned)(kk * 32) + khalf);
            unsigned a0, a1, a2, a3;
            ldsm4(a0, a1, a2, a3, sb + abase + aoff);
#pragma unroll
            for (int np = 0; np < 4; np++) {
                unsigned nrow = (unsigned)(np * 16 + lr + ((grp & 1) << 3));
                unsigned boff = swz(nrow * 128 + (unsigned)(kk * 32) + khalf);
                unsigned b0, b1, b2, b3;
                ldsm4(b0, b1, b2, b3, sb + bbase + boff);
                mma_h(acc[2*np],   a0, a1, a2, a3, b0, b2);
                mma_h(acc[2*np+1], a0, a1, a2, a3, b1, b3);
            }
        }
    }

    ((float*)(smc + SM_D))[tid] = dreg;
    __syncthreads();

    // epilogue: normalize, +bias, split to bf16 hi/lo for gemm2
    {
        const float* dsm = (const float*)(smc + SM_D);
        int r0 = m0 + (lane >> 2);
        int r1 = r0 + 8;
        float inv0 = 1.0f / (dsm[2*r0] + dsm[2*r0 + 1]);
        float inv1 = 1.0f / (dsm[2*r1] + dsm[2*r1 + 1]);
        int cb = (lane & 3) * 2;
#pragma unroll
        for (int nn = 0; nn < 8; nn++) {
            int col = nn * 8 + cb;
            float b0 = __ldg(bias_att + hd * HC + col);
            float b1 = __ldg(bias_att + hd * HC + col + 1);
            float v00 = acc[nn][0] * inv0 + b0, v01 = acc[nn][1] * inv0 + b1;
            float v10 = acc[nn][2] * inv1 + b0, v11 = acc[nn][3] * inv1 + b1;
            size_t o0 = ((size_t)(i0 + r0) * EMB + hd * HC + col) >> 1;
            size_t o1 = ((size_t)(i0 + r1) * EMB + hd * HC + col) >> 1;
            ((unsigned*)g_atthi)[o0] = bfpairhi(v00, v01);
            ((unsigned*)g_attlo)[o0] = bfpairlo(v00, v01);
            ((unsigned*)g_atthi)[o1] = bfpairhi(v10, v11);
            ((unsigned*)g_attlo)[o1] = bfpairlo(v10, v11);
        }
    }
}

// ---------------------------------------------------------------------------
// LayerNorm over last dim (256), one block per row.
// ---------------------------------------------------------------------------
__global__ __launch_bounds__(256) void ln_kernel(
    const float* __restrict__ gamma, const float* __restrict__ beta,
    float* __restrict__ out)
{
    __shared__ float red1[8], red2[8];
    int row = blockIdx.x;
    int tid = threadIdx.x;
    float v = g_y[row * EMB + tid];

    float s = v;
#pragma unroll
    for (int o = 16; o; o >>= 1) s += __shfl_xor_sync(0xffffffffu, s, o);
    if ((tid & 31) == 0) red1[tid >> 5] = s;
    __syncthreads();
    float mu = 0.f;
#pragma unroll
    for (int k = 0; k < 8; k++) mu += red1[k];
    mu *= (1.0f / EMB);

    float d = v - mu;
    float q = d * d;
#pragma unroll
    for (int o = 16; o; o >>= 1) q += __shfl_xor_sync(0xffffffffu, q, o);
    if ((tid & 31) == 0) red2[tid >> 5] = q;
    __syncthreads();
    float var = 0.f;
#pragma unroll
    for (int k = 0; k < 8; k++) var += red2[k];
    var *= (1.0f / EMB);

    out[row * EMB + tid] = d * rsqrtf(var + 1e-5f) * gamma[tid] + beta[tid];
}

// ---------------------------------------------------------------------------
extern "C" void kernel_launch(void* const* d_in, const int* in_sizes, int n_in,
                              void* d_out, int out_size)
{
    const float* x        = (const float*)d_in[0];
    const int*   adj      = (const int*)  d_in[1];
    const float* W_lin    = (const float*)d_in[2];
    const float* att_src  = (const float*)d_in[3];
    const float* att_dst  = (const float*)d_in[4];
    const float* bias_att = (const float*)d_in[5];
    const float* W_out    = (const float*)d_in[6];
    const float* b_out    = (const float*)d_in[7];
    const float* gamma    = (const float*)d_in[8];
    const float* beta     = (const float*)d_in[9];
    float* out = (float*)d_out;

    float *p_h, *p_y;
    cudaGetSymbolAddress((void**)&p_h, g_h);
    cudaGetSymbolAddress((void**)&p_y, g_y);
    __nv_bfloat16 *p_xhi, *p_xlo, *p_athi, *p_atlo, *p_wlhi, *p_wllo, *p_wohi, *p_wolo;
    cudaGetSymbolAddress((void**)&p_xhi,  g_xhi);
    cudaGetSymbolAddress((void**)&p_xlo,  g_xlo);
    cudaGetSymbolAddress((void**)&p_athi, g_atthi);
    cudaGetSymbolAddress((void**)&p_atlo, g_attlo);
    cudaGetSymbolAddress((void**)&p_wlhi, g_wlhi);
    cudaGetSymbolAddress((void**)&p_wllo, g_wllo);
    cudaGetSymbolAddress((void**)&p_wohi, g_wohi);
    cudaGetSymbolAddress((void**)&p_wolo, g_wolo);

    cudaFuncSetAttribute(gat_mma_kernel,  cudaFuncAttributeMaxDynamicSharedMemorySize, SM_TOT);
    cudaFuncSetAttribute(gemm_mma_kernel, cudaFuncAttributeMaxDynamicSharedMemorySize, GM_TOT);

    dim3 gemm_grid(EMB / 64, NN / 128);  // (4, 32) = 128 blocks

    // splits
    wsplit_kernel<<<128, 256>>>(W_lin, p_wlhi, p_wllo);
    wsplit_kernel<<<128, 256>>>(W_out, p_wohi, p_wolo);
    xsplit_kernel<<<2048, 256>>>(x);
    // 1) h = x @ W_lin  (bf16 3-product mma)
    gemm_mma_kernel<<<gemm_grid, 256, GM_TOT>>>(p_xhi, p_xlo, p_wlhi, p_wllo, nullptr, p_h);
    adjbits_kernel<<<NN, 256>>>(adj);
    prep_kernel<<<(NH * NN) / 8, 256>>>(att_src, att_dst);
    ht_kernel<<<dim3(NN / 64, NH), 256>>>();
    // 2) fp16 single-product masked-softmax aggregation (+bias_att) -> att hi/lo
    gat_mma_kernel<<<dim3(NN / 128, NH), 256, SM_TOT>>>(bias_att);
    // 3) y = att @ W_out + b_out  (bf16 3-product mma)
    gemm_mma_kernel<<<gemm_grid, 256, GM_TOT>>>(p_athi, p_atlo, p_wohi, p_wolo, b_out, p_y);
    // 4) LayerNorm -> out
    ln_kernel<<<NN, 256>>>(gamma, beta, out);
}